// round 1
// baseline (speedup 1.0000x reference)
#include <cuda_runtime.h>

#define B_    8
#define S_    1025
#define D_    768
#define H_    12
#define HD_   64
#define M_TOT (B_ * S_)   // 8200

// Scratch: Q/K/V in [B, H, S, HD] layout. Static __device__ arrays (no allocs).
__device__ float g_q[(size_t)B_ * H_ * S_ * HD_];
__device__ float g_k[(size_t)B_ * H_ * S_ * HD_];
__device__ float g_v[(size_t)B_ * H_ * S_ * HD_];

// ---------------------------------------------------------------------------
// QKV projection: out = X @ W + b, reshaped to [B, H, S, HD].
// 64x64 block tile, BK=16, 256 threads, 4x4 micro-tile.
// blockIdx.z selects Q/K/V. blockIdx.y == head (tile N == one head exactly).
// ---------------------------------------------------------------------------
__global__ __launch_bounds__(256) void qkv_kernel(
    const float* __restrict__ X,
    const float* __restrict__ Wq, const float* __restrict__ bq,
    const float* __restrict__ Wk, const float* __restrict__ bk,
    const float* __restrict__ Wv, const float* __restrict__ bv)
{
    __shared__ float Ast[16 * 68];  // A^T tile: Ast[k][m], pitch 68
    __shared__ float Bs [16 * 64];  // B tile:  Bs[k][n],  pitch 64

    const float* W;  const float* bias;  float* outb;
    int which = blockIdx.z;
    if (which == 0)      { W = Wq; bias = bq; outb = g_q; }
    else if (which == 1) { W = Wk; bias = bk; outb = g_k; }
    else                 { W = Wv; bias = bv; outb = g_v; }

    int tid = threadIdx.x;
    int tx  = tid & 15;        // 0..15 -> output cols tx*4..tx*4+3
    int ty  = tid >> 4;        // 0..15 -> output rows ty*4..ty*4+3
    int m0  = blockIdx.x * 64;
    int h   = blockIdx.y;
    int n0  = h * HD_;

    float acc[4][4];
#pragma unroll
    for (int i = 0; i < 4; i++)
#pragma unroll
        for (int j = 0; j < 4; j++) acc[i][j] = 0.f;

    for (int k0 = 0; k0 < D_; k0 += 16) {
        // Load A tile (64 rows of X, 16 k's), store transposed.
#pragma unroll
        for (int e = tid; e < 1024; e += 256) {
            int kk = e & 15, m = e >> 4;
            int gm = m0 + m;
            Ast[kk * 68 + m] = (gm < M_TOT) ? X[(size_t)gm * D_ + k0 + kk] : 0.f;
        }
        // Load B tile (16 k's, 64 n's), direct.
#pragma unroll
        for (int e = tid; e < 1024; e += 256) {
            int n = e & 63, kk = e >> 6;
            Bs[kk * 64 + n] = W[(size_t)(k0 + kk) * D_ + n0 + n];
        }
        __syncthreads();

#pragma unroll
        for (int kk = 0; kk < 16; kk++) {
            float4 a = *(const float4*)&Ast[kk * 68 + ty * 4];
            float4 b = *(const float4*)&Bs [kk * 64 + tx * 4];
            float av[4] = {a.x, a.y, a.z, a.w};
            float bv2[4] = {b.x, b.y, b.z, b.w};
#pragma unroll
            for (int i = 0; i < 4; i++)
#pragma unroll
                for (int j = 0; j < 4; j++)
                    acc[i][j] += av[i] * bv2[j];
        }
        __syncthreads();
    }

    // Epilogue: add bias, scatter to [B, H, S, HD].
    float bb[4];
#pragma unroll
    for (int j = 0; j < 4; j++) bb[j] = bias[n0 + tx * 4 + j];

#pragma unroll
    for (int i = 0; i < 4; i++) {
        int m = m0 + ty * 4 + i;
        if (m < M_TOT) {
            int bidx = m / S_;
            int s    = m - bidx * S_;
            float4 o;
            o.x = acc[i][0] + bb[0];
            o.y = acc[i][1] + bb[1];
            o.z = acc[i][2] + bb[2];
            o.w = acc[i][3] + bb[3];
            *(float4*)&outb[(((size_t)bidx * H_ + h) * S_ + s) * HD_ + tx * 4] = o;
        }
    }
}

// ---------------------------------------------------------------------------
// Flash-style attention. One block = (b, h, 64-query tile). 256 threads.
// Q,K staged transposed [d][row] pitch 68; V staged [row][d] pitch 68 (reuses
// K buffer); scores in smem [q][k] pitch 68; online softmax.
// ---------------------------------------------------------------------------
#define PIT 68
#define QT_OFF   0
#define KV_OFF   (64 * PIT)            // 4352
#define SS_OFF   (2 * 64 * PIT)        // 8704
#define MS_OFF   (3 * 64 * PIT)        // 13056
#define ATT_SMEM_BYTES ((3 * 64 * PIT + 3 * 64) * 4)   // 53760 B... (13248*4=52992)

__global__ __launch_bounds__(256) void attn_kernel(
    const float* __restrict__ rel_bias, float* __restrict__ out)
{
    extern __shared__ float sm[];
    float* Qt   = sm + QT_OFF;   // [64 d][PIT] holding Qt[d*PIT + row]
    float* KV   = sm + KV_OFF;   // K^T then V
    float* Ss   = sm + SS_OFF;   // scores [q][PIT]
    float* m_s  = sm + MS_OFF;
    float* l_s  = m_s + 64;
    float* al_s = l_s + 64;

    int tid = threadIdx.x;
    int tx  = tid & 15;         // head-dim / key cols: tx*4..+3
    int ty  = tid >> 4;         // query rows: ty*4..+3
    int b   = blockIdx.z;
    int h   = blockIdx.y;
    int q0  = blockIdx.x * 64;

    const size_t head_base = ((size_t)b * H_ + h) * S_ * HD_;
    const float* Qg = g_q + head_base;
    const float* Kg = g_k + head_base;
    const float* Vg = g_v + head_base;

    // Load Q tile transposed.
    for (int e = tid; e < 64 * 64; e += 256) {
        int r = e >> 6, d = e & 63;
        float qv = (q0 + r < S_) ? Qg[(size_t)(q0 + r) * HD_ + d] : 0.f;
        Qt[d * PIT + r] = qv;
    }
    if (tid < 64) { m_s[tid] = -1e30f; l_s[tid] = 0.f; }

    float acc[4][4];
#pragma unroll
    for (int i = 0; i < 4; i++)
#pragma unroll
        for (int j = 0; j < 4; j++) acc[i][j] = 0.f;

    __syncthreads();

    const float scale = 0.125f;  // 1/sqrt(64)

    for (int k0 = 0; k0 < S_; k0 += 64) {
        // Load K tile transposed into KV.
        for (int e = tid; e < 64 * 64; e += 256) {
            int r = e >> 6, d = e & 63;
            float kv = (k0 + r < S_) ? Kg[(size_t)(k0 + r) * HD_ + d] : 0.f;
            KV[d * PIT + r] = kv;
        }
        __syncthreads();

        // Scores: s[i][j] = sum_d Q[q][d] * K[k][d]
        float s[4][4];
#pragma unroll
        for (int i = 0; i < 4; i++)
#pragma unroll
            for (int j = 0; j < 4; j++) s[i][j] = 0.f;

#pragma unroll 8
        for (int d = 0; d < 64; d++) {
            float4 qa = *(const float4*)&Qt[d * PIT + ty * 4];
            float4 kb = *(const float4*)&KV[d * PIT + tx * 4];
            float qv[4] = {qa.x, qa.y, qa.z, qa.w};
            float kv[4] = {kb.x, kb.y, kb.z, kb.w};
#pragma unroll
            for (int i = 0; i < 4; i++)
#pragma unroll
                for (int j = 0; j < 4; j++)
                    s[i][j] += qv[i] * kv[j];
        }
#pragma unroll
        for (int i = 0; i < 4; i++) {
            float4 o = make_float4(s[i][0], s[i][1], s[i][2], s[i][3]);
            *(float4*)&Ss[(ty * 4 + i) * PIT + tx * 4] = o;
        }
        __syncthreads();   // Ss written; KV (K^T) no longer needed

        // Load V tile into KV (row-major [k][d]).
        for (int e = tid; e < 64 * 64; e += 256) {
            int r = e >> 6, d = e & 63;
            float vv = (k0 + r < S_) ? Vg[(size_t)(k0 + r) * HD_ + d] : 0.f;
            KV[r * PIT + d] = vv;
        }
        // Apply scale + rel_bias + key mask.
        for (int e = tid; e < 64 * 64; e += 256) {
            int r = e >> 6, c = e & 63;
            int qq = q0 + r, kk2 = k0 + c;
            float v;
            if (qq >= S_)       v = 0.f;
            else if (kk2 >= S_) v = -1e30f;
            else v = Ss[r * PIT + c] * scale +
                     rel_bias[((size_t)h * S_ + qq) * S_ + kk2];
            Ss[r * PIT + c] = v;
        }
        __syncthreads();

        // Online softmax, one thread per query row.
        if (tid < 64) {
            int r = tid;
            float mo = m_s[r];
            float mx = mo;
#pragma unroll 8
            for (int c = 0; c < 64; c++) mx = fmaxf(mx, Ss[r * PIT + c]);
            float alpha = __expf(mo - mx);
            float l = l_s[r] * alpha;
#pragma unroll 8
            for (int c = 0; c < 64; c++) {
                float p = __expf(Ss[r * PIT + c] - mx);
                Ss[r * PIT + c] = p;
                l += p;
            }
            m_s[r] = mx; l_s[r] = l; al_s[r] = alpha;
        }
        __syncthreads();

        // Rescale accumulators and add P @ V.
#pragma unroll
        for (int i = 0; i < 4; i++) {
            float a = al_s[ty * 4 + i];
#pragma unroll
            for (int j = 0; j < 4; j++) acc[i][j] *= a;
        }

#pragma unroll 4
        for (int kk = 0; kk < 64; kk += 4) {
            float4 p[4];
#pragma unroll
            for (int i = 0; i < 4; i++)
                p[i] = *(const float4*)&Ss[(ty * 4 + i) * PIT + kk];
            float4 v0 = *(const float4*)&KV[(kk + 0) * PIT + tx * 4];
            float4 v1 = *(const float4*)&KV[(kk + 1) * PIT + tx * 4];
            float4 v2 = *(const float4*)&KV[(kk + 2) * PIT + tx * 4];
            float4 v3 = *(const float4*)&KV[(kk + 3) * PIT + tx * 4];
#pragma unroll
            for (int i = 0; i < 4; i++) {
                acc[i][0] += p[i].x * v0.x + p[i].y * v1.x + p[i].z * v2.x + p[i].w * v3.x;
                acc[i][1] += p[i].x * v0.y + p[i].y * v1.y + p[i].z * v2.y + p[i].w * v3.y;
                acc[i][2] += p[i].x * v0.z + p[i].y * v1.z + p[i].z * v2.z + p[i].w * v3.z;
                acc[i][3] += p[i].x * v0.w + p[i].y * v1.w + p[i].z * v2.w + p[i].w * v3.w;
            }
        }
        __syncthreads();   // before next iteration overwrites KV/Ss
    }

    // Final normalize + write out[b, q, h*64 + d].
#pragma unroll
    for (int i = 0; i < 4; i++) {
        int q = q0 + ty * 4 + i;
        if (q < S_) {
            float inv = 1.f / l_s[ty * 4 + i];
            float4 o;
            o.x = acc[i][0] * inv;
            o.y = acc[i][1] * inv;
            o.z = acc[i][2] * inv;
            o.w = acc[i][3] * inv;
            *(float4*)&out[((size_t)b * S_ + q) * D_ + h * HD_ + tx * 4] = o;
        }
    }
}

// ---------------------------------------------------------------------------
extern "C" void kernel_launch(void* const* d_in, const int* in_sizes, int n_in,
                              void* d_out, int out_size)
{
    const float* hidden = (const float*)d_in[0];
    const float* bias   = (const float*)d_in[1];
    const float* Wq     = (const float*)d_in[2];
    const float* bq     = (const float*)d_in[3];
    const float* Wk     = (const float*)d_in[4];
    const float* bk     = (const float*)d_in[5];
    const float* Wv     = (const float*)d_in[6];
    const float* bv     = (const float*)d_in[7];
    float* out = (float*)d_out;

    static const int att_smem = (3 * 64 * PIT + 3 * 64) * sizeof(float); // 52992
    cudaFuncSetAttribute(attn_kernel,
                         cudaFuncAttributeMaxDynamicSharedMemorySize, att_smem);

    dim3 g1((M_TOT + 63) / 64, H_, 3);
    qkv_kernel<<<g1, 256>>>(hidden, Wq, bq, Wk, bk, Wv, bv);

    dim3 g2((S_ + 63) / 64, H_, B_);
    attn_kernel<<<g2, 256, att_smem>>>(bias, out);
}

// round 5
// speedup vs baseline: 1.4754x; 1.4754x over previous
#include <cuda_runtime.h>
#include <cuda_bf16.h>
#include <cstdint>

#define B_    8
#define S_    1025
#define D_    768
#define H_    12
#define HD_   64
#define M_TOT (B_ * S_)       // 8200
#define M_PAD 8320            // 65 * 128

// ---------------------------------------------------------------------------
// Device scratch
// ---------------------------------------------------------------------------
__device__ __align__(128) float g_q[(size_t)M_PAD * D_];
__device__ __align__(128) float g_k[(size_t)M_PAD * D_];
__device__ __align__(128) float g_v[(size_t)M_PAD * D_];
__device__ __align__(128) __nv_bfloat16 g_xhi[(size_t)M_PAD * D_];
__device__ __align__(128) __nv_bfloat16 g_xlo[(size_t)M_PAD * D_];
__device__ __align__(128) __nv_bfloat16 g_wthi[(size_t)3 * D_ * D_];
__device__ __align__(128) __nv_bfloat16 g_wtlo[(size_t)3 * D_ * D_];

// ---------------------------------------------------------------------------
// Base-ISA PTX helpers (NO sm_103a-gated instructions)
// ---------------------------------------------------------------------------
__device__ __forceinline__ uint32_t smem_u32(const void* p) {
    uint32_t a;
    asm("{ .reg .u64 t; cvta.to.shared.u64 t, %1; cvt.u32.u64 %0, t; }"
        : "=r"(a) : "l"(p));
    return a;
}

__device__ __forceinline__ void cp_async16(uint32_t dst, const void* src) {
    asm volatile("cp.async.cg.shared.global [%0], [%1], 16;\n"
                 :: "r"(dst), "l"(src));
}

__device__ __forceinline__ void ldsm4(uint32_t* r, uint32_t addr) {
    asm volatile("ldmatrix.sync.aligned.m8n8.x4.shared.b16 {%0,%1,%2,%3}, [%4];\n"
                 : "=r"(r[0]), "=r"(r[1]), "=r"(r[2]), "=r"(r[3]) : "r"(addr));
}

__device__ __forceinline__ void mma16816(float* d, const uint32_t* a,
                                         const uint32_t* b) {
    asm volatile(
        "mma.sync.aligned.m16n8k16.row.col.f32.bf16.bf16.f32 "
        "{%0,%1,%2,%3}, {%4,%5,%6,%7}, {%8,%9}, {%0,%1,%2,%3};\n"
        : "+f"(d[0]), "+f"(d[1]), "+f"(d[2]), "+f"(d[3])
        : "r"(a[0]), "r"(a[1]), "r"(a[2]), "r"(a[3]), "r"(b[0]), "r"(b[1]));
}

// ---------------------------------------------------------------------------
// Conversion: X -> (hi, lo) bf16, rows >= 8200 zeroed (pad to 8320)
// ---------------------------------------------------------------------------
__global__ __launch_bounds__(256) void convx_kernel(const float* __restrict__ X)
{
    size_t i = ((size_t)blockIdx.x * 256 + threadIdx.x) * 4;
    if (i >= (size_t)M_PAD * D_) return;
    size_t m = i / D_;
    float4 x = (m < M_TOT) ? *(const float4*)&X[i] : make_float4(0.f, 0.f, 0.f, 0.f);
    float xv[4] = {x.x, x.y, x.z, x.w};
    __nv_bfloat16 hi[4], lo[4];
#pragma unroll
    for (int j = 0; j < 4; j++) {
        hi[j] = __float2bfloat16(xv[j]);
        lo[j] = __float2bfloat16(xv[j] - __bfloat162float(hi[j]));
    }
    __nv_bfloat162 h01(hi[0], hi[1]), h23(hi[2], hi[3]);
    __nv_bfloat162 l01(lo[0], lo[1]), l23(lo[2], lo[3]);
    uint2 uh, ul;
    uh.x = *(uint32_t*)&h01; uh.y = *(uint32_t*)&h23;
    ul.x = *(uint32_t*)&l01; ul.y = *(uint32_t*)&l23;
    *(uint2*)&g_xhi[i] = uh;
    *(uint2*)&g_xlo[i] = ul;
}

// ---------------------------------------------------------------------------
// Conversion: W^T -> (hi, lo) bf16, tiled transpose. Wt[n][k] = W[k][n].
// ---------------------------------------------------------------------------
__global__ __launch_bounds__(256) void convw_kernel(
    const float* __restrict__ Wq, const float* __restrict__ Wk,
    const float* __restrict__ Wv)
{
    __shared__ float t[32][33];
    const float* W = (blockIdx.z == 0) ? Wq : (blockIdx.z == 1) ? Wk : Wv;
    __nv_bfloat16* oh = g_wthi + (size_t)blockIdx.z * D_ * D_;
    __nv_bfloat16* ol = g_wtlo + (size_t)blockIdx.z * D_ * D_;
    int k0 = blockIdx.x * 32, n0 = blockIdx.y * 32;
    for (int i = threadIdx.x; i < 1024; i += 256) {
        int r = i >> 5, c = i & 31;
        t[r][c] = W[(size_t)(k0 + r) * D_ + n0 + c];
    }
    __syncthreads();
    for (int i = threadIdx.x; i < 1024; i += 256) {
        int r = i >> 5, c = i & 31;        // r = n-local, c = k-local
        float x = t[c][r];
        __nv_bfloat16 h = __float2bfloat16(x);
        oh[(size_t)(n0 + r) * D_ + k0 + c] = h;
        ol[(size_t)(n0 + r) * D_ + k0 + c] =
            __float2bfloat16(x - __bfloat162float(h));
    }
}

// ---------------------------------------------------------------------------
// mma.sync split-bf16 GEMM: out = X @ W + b.
// CTA tile 128x128, BK=64, double-buffered cp.async, 8 warps (4m x 2n),
// warp tile 32x64. 3 MMA passes: Ah*Bh + Ah*Bl + Al*Bh, fp32 accum.
// grid = (65 m-tiles, 6 n-tiles, 3 matrices), 256 threads.
// smem stage layout (64KB): Ahi[128][64] | Alo | Bhi[128][64] | Blo
// Row = 128B (64 bf16), stored in 16B chunks with XOR swizzle (cc ^ (row&7)).
// ---------------------------------------------------------------------------
#define STAGE_BYTES 65536
#define GEMM_SMEM   (2 * STAGE_BYTES)

__global__ __launch_bounds__(256, 1) void gemm_kernel(
    const float* __restrict__ bq, const float* __restrict__ bk,
    const float* __restrict__ bv)
{
    extern __shared__ __align__(1024) unsigned char smg[];
    uint32_t sb = smem_u32(smg);
    int tid = threadIdx.x, wid = tid >> 5, lid = tid & 31;
    int warp_m = wid & 3, warp_n = wid >> 2;
    int m0 = blockIdx.x * 128;
    int n0 = blockIdx.y * 128;
    int mat = blockIdx.z;

    const __nv_bfloat16* Bhi = g_wthi + (size_t)mat * D_ * D_;
    const __nv_bfloat16* Blo = g_wtlo + (size_t)mat * D_ * D_;
    float* outp = (mat == 0) ? g_q : (mat == 1) ? g_k : g_v;
    const float* bias = (mat == 0) ? bq : (mat == 1) ? bk : bv;

    float acc[2][8][4];
#pragma unroll
    for (int f = 0; f < 2; f++)
#pragma unroll
        for (int nf = 0; nf < 8; nf++)
#pragma unroll
            for (int j = 0; j < 4; j++) acc[f][nf][j] = 0.f;

    // ---- stage loader: 16 cp.async(16B) per thread ----
    auto load_stage = [&](int c, int s) {
        int k0 = c * 64;
        uint32_t st = sb + s * STAGE_BYTES;
#pragma unroll
        for (int pass = 0; pass < 8; pass++) {
            int idx = pass * 256 + tid;          // A: 2048 chunks
            int sp = idx >> 10, rem = idx & 1023;
            int row = rem >> 3, cc = rem & 7;
            const __nv_bfloat16* src =
                (sp ? g_xlo : g_xhi) + (size_t)(m0 + row) * D_ + k0 + cc * 8;
            cp_async16(st + sp * 16384 + row * 128 + ((cc ^ (row & 7)) << 4), src);
        }
#pragma unroll
        for (int pass = 0; pass < 8; pass++) {
            int idx = pass * 256 + tid;          // B: 2048 chunks
            int sp = idx >> 10, rem = idx & 1023;
            int row = rem >> 3, cc = rem & 7;
            const __nv_bfloat16* src =
                (sp ? Blo : Bhi) + (size_t)(n0 + row) * D_ + k0 + cc * 8;
            cp_async16(st + 32768 + sp * 16384 + row * 128 + ((cc ^ (row & 7)) << 4), src);
        }
        asm volatile("cp.async.commit_group;\n" ::: "memory");
    };

    load_stage(0, 0);

    for (int c = 0; c < 12; c++) {
        int s = c & 1;
        if (c + 1 < 12) {
            load_stage(c + 1, s ^ 1);
            asm volatile("cp.async.wait_group 1;\n" ::: "memory");
        } else {
            asm volatile("cp.async.wait_group 0;\n" ::: "memory");
        }
        __syncthreads();

        uint32_t st  = sb + s * STAGE_BYTES;
        uint32_t bB  = st + 32768;
        int q = lid >> 3, r = lid & 7;

#pragma unroll
        for (int ks = 0; ks < 4; ks++) {
            // A fragments (hi + lo): 2 m16 frags each
            uint32_t ah[2][4], alr[2][4];
#pragma unroll
            for (int f = 0; f < 2; f++) {
                int mrow = warp_m * 32 + f * 16 + (q & 1) * 8 + r;
                int cc   = ks * 2 + (q >> 1);
                uint32_t addr = st + mrow * 128 + ((cc ^ (mrow & 7)) << 4);
                ldsm4(ah[f], addr);
                ldsm4(alr[f], addr + 16384);
            }
            // B hi fragments: 8 n8 frags (4 ldmatrix.x4)
            uint32_t bb[8][2];
#pragma unroll
            for (int g = 0; g < 4; g++) {
                int nrow = warp_n * 64 + g * 16 + (q >> 1) * 8 + r;
                int cc   = ks * 2 + (q & 1);
                uint32_t t[4];
                ldsm4(t, bB + nrow * 128 + ((cc ^ (nrow & 7)) << 4));
                bb[2 * g][0] = t[0]; bb[2 * g][1] = t[1];
                bb[2 * g + 1][0] = t[2]; bb[2 * g + 1][1] = t[3];
            }
#pragma unroll
            for (int f = 0; f < 2; f++)
#pragma unroll
                for (int nf = 0; nf < 8; nf++) {
                    mma16816(acc[f][nf], ah[f], bb[nf]);   // Ah*Bh
                    mma16816(acc[f][nf], alr[f], bb[nf]);  // Al*Bh
                }
            // B lo fragments into same regs
#pragma unroll
            for (int g = 0; g < 4; g++) {
                int nrow = warp_n * 64 + g * 16 + (q >> 1) * 8 + r;
                int cc   = ks * 2 + (q & 1);
                uint32_t t[4];
                ldsm4(t, bB + 16384 + nrow * 128 + ((cc ^ (nrow & 7)) << 4));
                bb[2 * g][0] = t[0]; bb[2 * g][1] = t[1];
                bb[2 * g + 1][0] = t[2]; bb[2 * g + 1][1] = t[3];
            }
#pragma unroll
            for (int f = 0; f < 2; f++)
#pragma unroll
                for (int nf = 0; nf < 8; nf++)
                    mma16816(acc[f][nf], ah[f], bb[nf]);   // Ah*Bl
        }
        __syncthreads();
    }

    // ---- epilogue: registers -> gmem + bias ----
    int g2 = lid >> 2, tg = lid & 3;
    int mbase = m0 + warp_m * 32;
    int nbase = n0 + warp_n * 64;
#pragma unroll
    for (int f = 0; f < 2; f++) {
#pragma unroll
        for (int nf = 0; nf < 8; nf++) {
            int n = nbase + nf * 8 + tg * 2;
            float b0 = bias[n], b1 = bias[n + 1];
            int m = mbase + f * 16 + g2;
            if (m < M_TOT) {
                float2 v = make_float2(acc[f][nf][0] + b0, acc[f][nf][1] + b1);
                *(float2*)&outp[(size_t)m * D_ + n] = v;
            }
            if (m + 8 < M_TOT) {
                float2 v = make_float2(acc[f][nf][2] + b0, acc[f][nf][3] + b1);
                *(float2*)&outp[(size_t)(m + 8) * D_ + n] = v;
            }
        }
    }
}

// ---------------------------------------------------------------------------
// Flash-style attention (scalar). Q/K/V layout [B*S, 768].
// ---------------------------------------------------------------------------
#define PIT 68
#define KV_OFF   (64 * PIT)
#define SS_OFF   (2 * 64 * PIT)
#define MS_OFF   (3 * 64 * PIT)

__global__ __launch_bounds__(256) void attn_kernel(
    const float* __restrict__ rel_bias, float* __restrict__ out)
{
    extern __shared__ float smf[];
    float* Qt   = smf;
    float* KV   = smf + KV_OFF;
    float* Ss   = smf + SS_OFF;
    float* m_s  = smf + MS_OFF;
    float* l_s  = m_s + 64;
    float* al_s = l_s + 64;

    int tid = threadIdx.x;
    int tx  = tid & 15;
    int ty  = tid >> 4;
    int b   = blockIdx.z;
    int h   = blockIdx.y;
    int q0  = blockIdx.x * 64;

    const size_t base = (size_t)b * S_ * D_ + h * HD_;
    const float* Qg = g_q + base;
    const float* Kg = g_k + base;
    const float* Vg = g_v + base;

    for (int e = tid; e < 64 * 64; e += 256) {
        int r = e >> 6, d = e & 63;
        float qv = (q0 + r < S_) ? Qg[(size_t)(q0 + r) * D_ + d] : 0.f;
        Qt[d * PIT + r] = qv;
    }
    if (tid < 64) { m_s[tid] = -1e30f; l_s[tid] = 0.f; }

    float acc[4][4];
#pragma unroll
    for (int i = 0; i < 4; i++)
#pragma unroll
        for (int j = 0; j < 4; j++) acc[i][j] = 0.f;

    __syncthreads();

    const float scale = 0.125f;

    for (int k0 = 0; k0 < S_; k0 += 64) {
        for (int e = tid; e < 64 * 64; e += 256) {
            int r = e >> 6, d = e & 63;
            float kv = (k0 + r < S_) ? Kg[(size_t)(k0 + r) * D_ + d] : 0.f;
            KV[d * PIT + r] = kv;
        }
        __syncthreads();

        float s[4][4];
#pragma unroll
        for (int i = 0; i < 4; i++)
#pragma unroll
            for (int j = 0; j < 4; j++) s[i][j] = 0.f;

#pragma unroll 8
        for (int d = 0; d < 64; d++) {
            float4 qa = *(const float4*)&Qt[d * PIT + ty * 4];
            float4 kb = *(const float4*)&KV[d * PIT + tx * 4];
            float qv[4] = {qa.x, qa.y, qa.z, qa.w};
            float kv[4] = {kb.x, kb.y, kb.z, kb.w};
#pragma unroll
            for (int i = 0; i < 4; i++)
#pragma unroll
                for (int j = 0; j < 4; j++)
                    s[i][j] += qv[i] * kv[j];
        }
#pragma unroll
        for (int i = 0; i < 4; i++) {
            float4 o = make_float4(s[i][0], s[i][1], s[i][2], s[i][3]);
            *(float4*)&Ss[(ty * 4 + i) * PIT + tx * 4] = o;
        }
        __syncthreads();

        for (int e = tid; e < 64 * 64; e += 256) {
            int r = e >> 6, d = e & 63;
            float vv = (k0 + r < S_) ? Vg[(size_t)(k0 + r) * D_ + d] : 0.f;
            KV[r * PIT + d] = vv;
        }
        for (int e = tid; e < 64 * 64; e += 256) {
            int r = e >> 6, c = e & 63;
            int qq = q0 + r, kk2 = k0 + c;
            float v;
            if (qq >= S_)       v = 0.f;
            else if (kk2 >= S_) v = -1e30f;
            else v = Ss[r * PIT + c] * scale +
                     rel_bias[((size_t)h * S_ + qq) * S_ + kk2];
            Ss[r * PIT + c] = v;
        }
        __syncthreads();

        if (tid < 64) {
            int r = tid;
            float mo = m_s[r];
            float mx = mo;
#pragma unroll 8
            for (int c = 0; c < 64; c++) mx = fmaxf(mx, Ss[r * PIT + c]);
            float alpha = __expf(mo - mx);
            float l = l_s[r] * alpha;
#pragma unroll 8
            for (int c = 0; c < 64; c++) {
                float p = __expf(Ss[r * PIT + c] - mx);
                Ss[r * PIT + c] = p;
                l += p;
            }
            m_s[r] = mx; l_s[r] = l; al_s[r] = alpha;
        }
        __syncthreads();

#pragma unroll
        for (int i = 0; i < 4; i++) {
            float a = al_s[ty * 4 + i];
#pragma unroll
            for (int j = 0; j < 4; j++) acc[i][j] *= a;
        }

#pragma unroll 4
        for (int kk = 0; kk < 64; kk += 4) {
            float4 p[4];
#pragma unroll
            for (int i = 0; i < 4; i++)
                p[i] = *(const float4*)&Ss[(ty * 4 + i) * PIT + kk];
            float4 v0 = *(const float4*)&KV[(kk + 0) * PIT + tx * 4];
            float4 v1 = *(const float4*)&KV[(kk + 1) * PIT + tx * 4];
            float4 v2 = *(const float4*)&KV[(kk + 2) * PIT + tx * 4];
            float4 v3 = *(const float4*)&KV[(kk + 3) * PIT + tx * 4];
#pragma unroll
            for (int i = 0; i < 4; i++) {
                acc[i][0] += p[i].x * v0.x + p[i].y * v1.x + p[i].z * v2.x + p[i].w * v3.x;
                acc[i][1] += p[i].x * v0.y + p[i].y * v1.y + p[i].z * v2.y + p[i].w * v3.y;
                acc[i][2] += p[i].x * v0.z + p[i].y * v1.z + p[i].z * v2.z + p[i].w * v3.z;
                acc[i][3] += p[i].x * v0.w + p[i].y * v1.w + p[i].z * v2.w + p[i].w * v3.w;
            }
        }
        __syncthreads();
    }

#pragma unroll
    for (int i = 0; i < 4; i++) {
        int q = q0 + ty * 4 + i;
        if (q < S_) {
            float inv = 1.f / l_s[ty * 4 + i];
            float4 o;
            o.x = acc[i][0] * inv;
            o.y = acc[i][1] * inv;
            o.z = acc[i][2] * inv;
            o.w = acc[i][3] * inv;
            *(float4*)&out[((size_t)b * S_ + q) * D_ + h * HD_ + tx * 4] = o;
        }
    }
}

// ---------------------------------------------------------------------------
extern "C" void kernel_launch(void* const* d_in, const int* in_sizes, int n_in,
                              void* d_out, int out_size)
{
    const float* hidden = (const float*)d_in[0];
    const float* bias   = (const float*)d_in[1];
    const float* Wq     = (const float*)d_in[2];
    const float* bq     = (const float*)d_in[3];
    const float* Wk     = (const float*)d_in[4];
    const float* bk     = (const float*)d_in[5];
    const float* Wv     = (const float*)d_in[6];
    const float* bv     = (const float*)d_in[7];
    float* out = (float*)d_out;

    static const int att_smem = (3 * 64 * PIT + 3 * 64) * sizeof(float);
    cudaFuncSetAttribute(attn_kernel,
                         cudaFuncAttributeMaxDynamicSharedMemorySize, att_smem);
    cudaFuncSetAttribute(gemm_kernel,
                         cudaFuncAttributeMaxDynamicSharedMemorySize, GEMM_SMEM);

    convx_kernel<<<(M_PAD * D_ / 4 + 255) / 256, 256>>>(hidden);
    convw_kernel<<<dim3(24, 24, 3), 256>>>(Wq, Wk, Wv);
    gemm_kernel<<<dim3(65, 6, 3), 256, GEMM_SMEM>>>(bq, bk, bv);

    dim3 g2((S_ + 63) / 64, H_, B_);
    attn_kernel<<<g2, 256, att_smem>>>(bias, out);
}

// round 6
// speedup vs baseline: 1.6517x; 1.1195x over previous
#include <cuda_runtime.h>
#include <cuda_bf16.h>
#include <cstdint>

#define B_    8
#define S_    1025
#define D_    768
#define H_    12
#define HD_   64
#define M_TOT (B_ * S_)       // 8200
#define M_PAD 8320            // 65 * 128

// ---------------------------------------------------------------------------
// Device scratch: Q (pre-scaled by 0.125), K, V as split-bf16 hi/lo, [B*S][768]
// ---------------------------------------------------------------------------
__device__ __align__(128) __nv_bfloat16 g_qhi[(size_t)M_PAD * D_];
__device__ __align__(128) __nv_bfloat16 g_qlo[(size_t)M_PAD * D_];
__device__ __align__(128) __nv_bfloat16 g_khi[(size_t)M_PAD * D_];
__device__ __align__(128) __nv_bfloat16 g_klo[(size_t)M_PAD * D_];
__device__ __align__(128) __nv_bfloat16 g_vhi[(size_t)M_PAD * D_];
__device__ __align__(128) __nv_bfloat16 g_vlo[(size_t)M_PAD * D_];
__device__ __align__(128) __nv_bfloat16 g_xhi[(size_t)M_PAD * D_];
__device__ __align__(128) __nv_bfloat16 g_xlo[(size_t)M_PAD * D_];
__device__ __align__(128) __nv_bfloat16 g_wthi[(size_t)3 * D_ * D_];
__device__ __align__(128) __nv_bfloat16 g_wtlo[(size_t)3 * D_ * D_];

// ---------------------------------------------------------------------------
// Base-ISA PTX helpers
// ---------------------------------------------------------------------------
__device__ __forceinline__ uint32_t smem_u32(const void* p) {
    uint32_t a;
    asm("{ .reg .u64 t; cvta.to.shared.u64 t, %1; cvt.u32.u64 %0, t; }"
        : "=r"(a) : "l"(p));
    return a;
}
__device__ __forceinline__ void cp_async16(uint32_t dst, const void* src) {
    asm volatile("cp.async.cg.shared.global [%0], [%1], 16;\n"
                 :: "r"(dst), "l"(src));
}
__device__ __forceinline__ void ldsm4(uint32_t* r, uint32_t addr) {
    asm volatile("ldmatrix.sync.aligned.m8n8.x4.shared.b16 {%0,%1,%2,%3}, [%4];\n"
                 : "=r"(r[0]), "=r"(r[1]), "=r"(r[2]), "=r"(r[3]) : "r"(addr));
}
__device__ __forceinline__ void ldsm4t(uint32_t* r, uint32_t addr) {
    asm volatile("ldmatrix.sync.aligned.m8n8.x4.trans.shared.b16 {%0,%1,%2,%3}, [%4];\n"
                 : "=r"(r[0]), "=r"(r[1]), "=r"(r[2]), "=r"(r[3]) : "r"(addr));
}
__device__ __forceinline__ void mma16816(float* d, const uint32_t* a,
                                         const uint32_t* b) {
    asm volatile(
        "mma.sync.aligned.m16n8k16.row.col.f32.bf16.bf16.f32 "
        "{%0,%1,%2,%3}, {%4,%5,%6,%7}, {%8,%9}, {%0,%1,%2,%3};\n"
        : "+f"(d[0]), "+f"(d[1]), "+f"(d[2]), "+f"(d[3])
        : "r"(a[0]), "r"(a[1]), "r"(a[2]), "r"(a[3]), "r"(b[0]), "r"(b[1]));
}
__device__ __forceinline__ void split2(float x, float y, uint32_t& hi, uint32_t& lo) {
    __nv_bfloat162 h = __floats2bfloat162_rn(x, y);
    float2 f = __bfloat1622float2(h);
    __nv_bfloat162 l = __floats2bfloat162_rn(x - f.x, y - f.y);
    hi = *(uint32_t*)&h;
    lo = *(uint32_t*)&l;
}

// ---------------------------------------------------------------------------
// Conversion: X -> (hi, lo) bf16, rows >= 8200 zeroed (pad to 8320)
// ---------------------------------------------------------------------------
__global__ __launch_bounds__(256) void convx_kernel(const float* __restrict__ X)
{
    size_t i = ((size_t)blockIdx.x * 256 + threadIdx.x) * 4;
    if (i >= (size_t)M_PAD * D_) return;
    size_t m = i / D_;
    float4 x = (m < M_TOT) ? *(const float4*)&X[i] : make_float4(0.f, 0.f, 0.f, 0.f);
    uint2 uh, ul;
    split2(x.x, x.y, uh.x, ul.x);
    split2(x.z, x.w, uh.y, ul.y);
    *(uint2*)&g_xhi[i] = uh;
    *(uint2*)&g_xlo[i] = ul;
}

// ---------------------------------------------------------------------------
// Conversion: W^T -> (hi, lo) bf16, tiled transpose. Wt[n][k] = W[k][n].
// ---------------------------------------------------------------------------
__global__ __launch_bounds__(256) void convw_kernel(
    const float* __restrict__ Wq, const float* __restrict__ Wk,
    const float* __restrict__ Wv)
{
    __shared__ float t[32][33];
    const float* W = (blockIdx.z == 0) ? Wq : (blockIdx.z == 1) ? Wk : Wv;
    __nv_bfloat16* oh = g_wthi + (size_t)blockIdx.z * D_ * D_;
    __nv_bfloat16* ol = g_wtlo + (size_t)blockIdx.z * D_ * D_;
    int k0 = blockIdx.x * 32, n0 = blockIdx.y * 32;
    for (int i = threadIdx.x; i < 1024; i += 256) {
        int r = i >> 5, c = i & 31;
        t[r][c] = W[(size_t)(k0 + r) * D_ + n0 + c];
    }
    __syncthreads();
    for (int i = threadIdx.x; i < 1024; i += 256) {
        int r = i >> 5, c = i & 31;
        float x = t[c][r];
        __nv_bfloat16 h = __float2bfloat16(x);
        oh[(size_t)(n0 + r) * D_ + k0 + c] = h;
        ol[(size_t)(n0 + r) * D_ + k0 + c] =
            __float2bfloat16(x - __bfloat162float(h));
    }
}

// ---------------------------------------------------------------------------
// mma.sync split-bf16 GEMM (as R5, validated) — epilogue now emits bf16 hi/lo
// for Q (x0.125), K, V.
// ---------------------------------------------------------------------------
#define STAGE_BYTES 65536
#define GEMM_SMEM   (2 * STAGE_BYTES)

__global__ __launch_bounds__(256, 1) void gemm_kernel(
    const float* __restrict__ bq, const float* __restrict__ bk,
    const float* __restrict__ bv)
{
    extern __shared__ __align__(1024) unsigned char smg[];
    uint32_t sb = smem_u32(smg);
    int tid = threadIdx.x, wid = tid >> 5, lid = tid & 31;
    int warp_m = wid & 3, warp_n = wid >> 2;
    int m0 = blockIdx.x * 128;
    int n0 = blockIdx.y * 128;
    int mat = blockIdx.z;

    const __nv_bfloat16* Bhi = g_wthi + (size_t)mat * D_ * D_;
    const __nv_bfloat16* Blo = g_wtlo + (size_t)mat * D_ * D_;
    __nv_bfloat16* ohi = (mat == 0) ? g_qhi : (mat == 1) ? g_khi : g_vhi;
    __nv_bfloat16* olo = (mat == 0) ? g_qlo : (mat == 1) ? g_klo : g_vlo;
    const float* bias = (mat == 0) ? bq : (mat == 1) ? bk : bv;
    const float osc = (mat == 0) ? 0.125f : 1.0f;

    float acc[2][8][4];
#pragma unroll
    for (int f = 0; f < 2; f++)
#pragma unroll
        for (int nf = 0; nf < 8; nf++)
#pragma unroll
            for (int j = 0; j < 4; j++) acc[f][nf][j] = 0.f;

    auto load_stage = [&](int c, int s) {
        int k0 = c * 64;
        uint32_t st = sb + s * STAGE_BYTES;
#pragma unroll
        for (int pass = 0; pass < 8; pass++) {
            int idx = pass * 256 + tid;
            int sp = idx >> 10, rem = idx & 1023;
            int row = rem >> 3, cc = rem & 7;
            const __nv_bfloat16* src =
                (sp ? g_xlo : g_xhi) + (size_t)(m0 + row) * D_ + k0 + cc * 8;
            cp_async16(st + sp * 16384 + row * 128 + ((cc ^ (row & 7)) << 4), src);
        }
#pragma unroll
        for (int pass = 0; pass < 8; pass++) {
            int idx = pass * 256 + tid;
            int sp = idx >> 10, rem = idx & 1023;
            int row = rem >> 3, cc = rem & 7;
            const __nv_bfloat16* src =
                (sp ? Blo : Bhi) + (size_t)(n0 + row) * D_ + k0 + cc * 8;
            cp_async16(st + 32768 + sp * 16384 + row * 128 + ((cc ^ (row & 7)) << 4), src);
        }
        asm volatile("cp.async.commit_group;\n" ::: "memory");
    };

    load_stage(0, 0);

    for (int c = 0; c < 12; c++) {
        int s = c & 1;
        if (c + 1 < 12) {
            load_stage(c + 1, s ^ 1);
            asm volatile("cp.async.wait_group 1;\n" ::: "memory");
        } else {
            asm volatile("cp.async.wait_group 0;\n" ::: "memory");
        }
        __syncthreads();

        uint32_t st  = sb + s * STAGE_BYTES;
        uint32_t bB  = st + 32768;
        int q = lid >> 3, r = lid & 7;

#pragma unroll
        for (int ks = 0; ks < 4; ks++) {
            uint32_t ah[2][4], alr[2][4];
#pragma unroll
            for (int f = 0; f < 2; f++) {
                int mrow = warp_m * 32 + f * 16 + (q & 1) * 8 + r;
                int cc   = ks * 2 + (q >> 1);
                uint32_t addr = st + mrow * 128 + ((cc ^ (mrow & 7)) << 4);
                ldsm4(ah[f], addr);
                ldsm4(alr[f], addr + 16384);
            }
            uint32_t bb[8][2];
#pragma unroll
            for (int g = 0; g < 4; g++) {
                int nrow = warp_n * 64 + g * 16 + (q >> 1) * 8 + r;
                int cc   = ks * 2 + (q & 1);
                uint32_t t[4];
                ldsm4(t, bB + nrow * 128 + ((cc ^ (nrow & 7)) << 4));
                bb[2 * g][0] = t[0]; bb[2 * g][1] = t[1];
                bb[2 * g + 1][0] = t[2]; bb[2 * g + 1][1] = t[3];
            }
#pragma unroll
            for (int f = 0; f < 2; f++)
#pragma unroll
                for (int nf = 0; nf < 8; nf++) {
                    mma16816(acc[f][nf], ah[f], bb[nf]);
                    mma16816(acc[f][nf], alr[f], bb[nf]);
                }
#pragma unroll
            for (int g = 0; g < 4; g++) {
                int nrow = warp_n * 64 + g * 16 + (q >> 1) * 8 + r;
                int cc   = ks * 2 + (q & 1);
                uint32_t t[4];
                ldsm4(t, bB + 16384 + nrow * 128 + ((cc ^ (nrow & 7)) << 4));
                bb[2 * g][0] = t[0]; bb[2 * g][1] = t[1];
                bb[2 * g + 1][0] = t[2]; bb[2 * g + 1][1] = t[3];
            }
#pragma unroll
            for (int f = 0; f < 2; f++)
#pragma unroll
                for (int nf = 0; nf < 8; nf++)
                    mma16816(acc[f][nf], ah[f], bb[nf]);
        }
        __syncthreads();
    }

    // ---- epilogue: split-bf16 hi/lo + bias (+0.125 scale for Q) ----
    int g2 = lid >> 2, tg = lid & 3;
    int mbase = m0 + warp_m * 32;
    int nbase = n0 + warp_n * 64;
#pragma unroll
    for (int f = 0; f < 2; f++) {
#pragma unroll
        for (int nf = 0; nf < 8; nf++) {
            int n = nbase + nf * 8 + tg * 2;
            float b0 = bias[n], b1 = bias[n + 1];
            int m = mbase + f * 16 + g2;
            if (m < M_TOT) {
                uint32_t h, l;
                split2((acc[f][nf][0] + b0) * osc, (acc[f][nf][1] + b1) * osc, h, l);
                *(uint32_t*)&ohi[(size_t)m * D_ + n] = h;
                *(uint32_t*)&olo[(size_t)m * D_ + n] = l;
            }
            if (m + 8 < M_TOT) {
                uint32_t h, l;
                split2((acc[f][nf][2] + b0) * osc, (acc[f][nf][3] + b1) * osc, h, l);
                *(uint32_t*)&ohi[(size_t)(m + 8) * D_ + n] = h;
                *(uint32_t*)&olo[(size_t)(m + 8) * D_ + n] = l;
            }
        }
    }
}

// ---------------------------------------------------------------------------
// Tensor-core flash attention. Block = (128 q, b, h), 8 warps; warp owns 16 q.
// Split-bf16 3-MMA for both S=Q'K^T and O=PV. Online softmax in frag layout.
// smem: 2 x 32KB KV stages (Khi|Klo|Vhi|Vlo, 8KB each); Q staged in buf0 once.
// ---------------------------------------------------------------------------
#define QT   128
#define NKT  17
#define ATT_SMEM 65536

__global__ __launch_bounds__(256, 1) void attn_kernel(
    const float* __restrict__ rel_bias, float* __restrict__ out)
{
    extern __shared__ __align__(1024) unsigned char sma[];
    uint32_t sb = smem_u32(sma);
    int tid = threadIdx.x, wid = tid >> 5, lid = tid & 31;
    int qq = lid >> 3, r = lid & 7;       // ldmatrix lane decomposition
    int g  = lid >> 2, t = lid & 3;       // mma accum lane decomposition
    int q0 = blockIdx.x * QT;
    int b  = blockIdx.y;
    int h  = blockIdx.z;

    const __nv_bfloat16* arrp[4] = {g_khi, g_klo, g_vhi, g_vlo};

    auto load_q = [&]() {
#pragma unroll
        for (int p = 0; p < 8; p++) {
            int idx = p * 256 + tid;                 // 2048 chunks
            int sp = idx >> 10, rem = idx & 1023;
            int row = rem >> 3, cc = rem & 7;
            int gq = q0 + row; if (gq > S_ - 1) gq = S_ - 1;
            const __nv_bfloat16* src = (sp ? g_qlo : g_qhi)
                + (size_t)(b * S_ + gq) * D_ + h * HD_ + cc * 8;
            cp_async16(sb + sp * 16384 + row * 128 + ((cc ^ (row & 7)) << 4), src);
        }
        asm volatile("cp.async.commit_group;\n" ::: "memory");
    };
    auto load_kv = [&](int kt, int s) {
#pragma unroll
        for (int p = 0; p < 8; p++) {
            int idx = p * 256 + tid;                 // 2048 chunks
            int a = idx >> 9, rem = idx & 511;
            int row = rem >> 3, cc = rem & 7;
            int gk = kt * 64 + row; if (gk > S_ - 1) gk = S_ - 1;
            const __nv_bfloat16* src = arrp[a]
                + (size_t)(b * S_ + gk) * D_ + h * HD_ + cc * 8;
            cp_async16(sb + s * 32768 + a * 8192 + row * 128 + ((cc ^ (row & 7)) << 4), src);
        }
        asm volatile("cp.async.commit_group;\n" ::: "memory");
    };

    load_q();
    load_kv(0, 1);
    asm volatile("cp.async.wait_group 1;\n" ::: "memory");
    __syncthreads();

    // Extract Q A-fragments (hi+lo) to registers.
    uint32_t qh[4][4], qlr[4][4];
#pragma unroll
    for (int ks = 0; ks < 4; ks++) {
        int mrow = wid * 16 + (qq & 1) * 8 + r;
        int cc = ks * 2 + (qq >> 1);
        uint32_t addr = sb + mrow * 128 + ((cc ^ (mrow & 7)) << 4);
        ldsm4(qh[ks], addr);
        ldsm4(qlr[ks], addr + 16384);
    }
    __syncthreads();    // buf0 now reusable for KV

    float o[8][4];
#pragma unroll
    for (int nt = 0; nt < 8; nt++)
#pragma unroll
        for (int j = 0; j < 4; j++) o[nt][j] = 0.f;
    float rm0 = -1e30f, rm1 = -1e30f, rl0 = 0.f, rl1 = 0.f;

    int rq0 = q0 + wid * 16 + g;
    int rq1 = rq0 + 8;
    const float* bp0 = rel_bias + ((size_t)h * S_ + min(rq0, S_ - 1)) * S_;
    const float* bp1 = rel_bias + ((size_t)h * S_ + min(rq1, S_ - 1)) * S_;

    for (int it = 0; it < NKT; it++) {
        int s = (it + 1) & 1;
        __syncthreads();                       // prior compute done -> s^1 reusable
        if (it + 1 < NKT) {
            load_kv(it + 1, s ^ 1);
            asm volatile("cp.async.wait_group 1;\n" ::: "memory");
        } else {
            asm volatile("cp.async.wait_group 0;\n" ::: "memory");
        }
        __syncthreads();                       // stage s visible to all

        uint32_t kb = sb + s * 32768;
        float sc[8][4];
#pragma unroll
        for (int nt = 0; nt < 8; nt++)
#pragma unroll
            for (int j = 0; j < 4; j++) sc[nt][j] = 0.f;

        // ---- S = Q' K^T (3-MMA split) ----
#pragma unroll
        for (int ks = 0; ks < 4; ks++) {
            uint32_t bf[8][2];
#pragma unroll
            for (int gg = 0; gg < 4; gg++) {
                int nrow = gg * 16 + (qq >> 1) * 8 + r;
                int cc = ks * 2 + (qq & 1);
                uint32_t tt[4];
                ldsm4(tt, kb + nrow * 128 + ((cc ^ (nrow & 7)) << 4));
                bf[2 * gg][0] = tt[0]; bf[2 * gg][1] = tt[1];
                bf[2 * gg + 1][0] = tt[2]; bf[2 * gg + 1][1] = tt[3];
            }
#pragma unroll
            for (int nt = 0; nt < 8; nt++) {
                mma16816(sc[nt], qh[ks], bf[nt]);
                mma16816(sc[nt], qlr[ks], bf[nt]);
            }
#pragma unroll
            for (int gg = 0; gg < 4; gg++) {
                int nrow = gg * 16 + (qq >> 1) * 8 + r;
                int cc = ks * 2 + (qq & 1);
                uint32_t tt[4];
                ldsm4(tt, kb + 8192 + nrow * 128 + ((cc ^ (nrow & 7)) << 4));
                bf[2 * gg][0] = tt[0]; bf[2 * gg][1] = tt[1];
                bf[2 * gg + 1][0] = tt[2]; bf[2 * gg + 1][1] = tt[3];
            }
#pragma unroll
            for (int nt = 0; nt < 8; nt++)
                mma16816(sc[nt], qh[ks], bf[nt]);
        }

        // ---- bias + mask + online softmax ----
        int kbase = it * 64;
        float nx0 = rm0, nx1 = rm1;
#pragma unroll
        for (int nt = 0; nt < 8; nt++) {
            int kc = kbase + nt * 8 + 2 * t;
            bool v0 = kc < S_, v1 = (kc + 1) < S_;
            float b00 = v0 ? bp0[kc] : 0.f;
            float b01 = v1 ? bp0[kc + 1] : 0.f;
            float b10 = v0 ? bp1[kc] : 0.f;
            float b11 = v1 ? bp1[kc + 1] : 0.f;
            sc[nt][0] = v0 ? sc[nt][0] + b00 : -1e30f;
            sc[nt][1] = v1 ? sc[nt][1] + b01 : -1e30f;
            sc[nt][2] = v0 ? sc[nt][2] + b10 : -1e30f;
            sc[nt][3] = v1 ? sc[nt][3] + b11 : -1e30f;
            nx0 = fmaxf(nx0, fmaxf(sc[nt][0], sc[nt][1]));
            nx1 = fmaxf(nx1, fmaxf(sc[nt][2], sc[nt][3]));
        }
        nx0 = fmaxf(nx0, __shfl_xor_sync(0xffffffffu, nx0, 1));
        nx0 = fmaxf(nx0, __shfl_xor_sync(0xffffffffu, nx0, 2));
        nx1 = fmaxf(nx1, __shfl_xor_sync(0xffffffffu, nx1, 1));
        nx1 = fmaxf(nx1, __shfl_xor_sync(0xffffffffu, nx1, 2));
        float a0 = __expf(rm0 - nx0), a1 = __expf(rm1 - nx1);
        rm0 = nx0; rm1 = nx1;
        float s0 = 0.f, s1 = 0.f;
#pragma unroll
        for (int nt = 0; nt < 8; nt++) {
            sc[nt][0] = __expf(sc[nt][0] - nx0);
            sc[nt][1] = __expf(sc[nt][1] - nx0);
            sc[nt][2] = __expf(sc[nt][2] - nx1);
            sc[nt][3] = __expf(sc[nt][3] - nx1);
            s0 += sc[nt][0] + sc[nt][1];
            s1 += sc[nt][2] + sc[nt][3];
        }
        s0 += __shfl_xor_sync(0xffffffffu, s0, 1);
        s0 += __shfl_xor_sync(0xffffffffu, s0, 2);
        s1 += __shfl_xor_sync(0xffffffffu, s1, 1);
        s1 += __shfl_xor_sync(0xffffffffu, s1, 2);
        rl0 = rl0 * a0 + s0;
        rl1 = rl1 * a1 + s1;
#pragma unroll
        for (int nt = 0; nt < 8; nt++) {
            o[nt][0] *= a0; o[nt][1] *= a0; o[nt][2] *= a1; o[nt][3] *= a1;
        }

        // ---- O += P V (3-MMA split; P frags built in registers) ----
        uint32_t vb = kb + 16384;
#pragma unroll
        for (int ks = 0; ks < 4; ks++) {
            uint32_t ah[4], al[4];
            split2(sc[2 * ks][0],     sc[2 * ks][1],     ah[0], al[0]);
            split2(sc[2 * ks][2],     sc[2 * ks][3],     ah[1], al[1]);
            split2(sc[2 * ks + 1][0], sc[2 * ks + 1][1], ah[2], al[2]);
            split2(sc[2 * ks + 1][2], sc[2 * ks + 1][3], ah[3], al[3]);

            uint32_t bf[8][2];
#pragma unroll
            for (int dp = 0; dp < 4; dp++) {
                int row = ks * 16 + (qq & 1) * 8 + r;
                int cc = dp * 2 + (qq >> 1);
                uint32_t tt[4];
                ldsm4t(tt, vb + row * 128 + ((cc ^ (row & 7)) << 4));
                bf[2 * dp][0] = tt[0]; bf[2 * dp][1] = tt[1];
                bf[2 * dp + 1][0] = tt[2]; bf[2 * dp + 1][1] = tt[3];
            }
#pragma unroll
            for (int nt = 0; nt < 8; nt++) {
                mma16816(o[nt], ah, bf[nt]);
                mma16816(o[nt], al, bf[nt]);
            }
#pragma unroll
            for (int dp = 0; dp < 4; dp++) {
                int row = ks * 16 + (qq & 1) * 8 + r;
                int cc = dp * 2 + (qq >> 1);
                uint32_t tt[4];
                ldsm4t(tt, vb + 8192 + row * 128 + ((cc ^ (row & 7)) << 4));
                bf[2 * dp][0] = tt[0]; bf[2 * dp][1] = tt[1];
                bf[2 * dp + 1][0] = tt[2]; bf[2 * dp + 1][1] = tt[3];
            }
#pragma unroll
            for (int nt = 0; nt < 8; nt++)
                mma16816(o[nt], ah, bf[nt]);
        }
    }

    // ---- finalize + store ----
    float i0 = 1.f / rl0, i1 = 1.f / rl1;
#pragma unroll
    for (int nt = 0; nt < 8; nt++) {
        int dc = h * HD_ + nt * 8 + 2 * t;
        if (rq0 < S_)
            *(float2*)&out[((size_t)b * S_ + rq0) * D_ + dc] =
                make_float2(o[nt][0] * i0, o[nt][1] * i0);
        if (rq1 < S_)
            *(float2*)&out[((size_t)b * S_ + rq1) * D_ + dc] =
                make_float2(o[nt][2] * i1, o[nt][3] * i1);
    }
}

// ---------------------------------------------------------------------------
extern "C" void kernel_launch(void* const* d_in, const int* in_sizes, int n_in,
                              void* d_out, int out_size)
{
    const float* hidden = (const float*)d_in[0];
    const float* bias   = (const float*)d_in[1];
    const float* Wq     = (const float*)d_in[2];
    const float* bq     = (const float*)d_in[3];
    const float* Wk     = (const float*)d_in[4];
    const float* bk     = (const float*)d_in[5];
    const float* Wv     = (const float*)d_in[6];
    const float* bv     = (const float*)d_in[7];
    float* out = (float*)d_out;

    cudaFuncSetAttribute(gemm_kernel,
                         cudaFuncAttributeMaxDynamicSharedMemorySize, GEMM_SMEM);
    cudaFuncSetAttribute(attn_kernel,
                         cudaFuncAttributeMaxDynamicSharedMemorySize, ATT_SMEM);

    convx_kernel<<<(M_PAD * D_ / 4 + 255) / 256, 256>>>(hidden);
    convw_kernel<<<dim3(24, 24, 3), 256>>>(Wq, Wk, Wv);
    gemm_kernel<<<dim3(65, 6, 3), 256, GEMM_SMEM>>>(bq, bk, bv);

    dim3 g2((S_ + QT - 1) / QT, B_, H_);   // (9, 8, 12); h slowest -> bias L2 reuse
    attn_kernel<<<g2, 256, ATT_SMEM>>>(bias, out);
}

// round 8
// speedup vs baseline: 2.6457x; 1.6018x over previous
#include <cuda_runtime.h>
#include <cuda_bf16.h>
#include <cstdint>

#define B_    8
#define S_    1025
#define D_    768
#define H_    12
#define HD_   64
#define M_TOT (B_ * S_)       // 8200
#define M_PAD 8320            // 65 * 128

// ---------------------------------------------------------------------------
// Device scratch: Q (pre-scaled by 0.125), K, V as split-bf16 hi/lo, [B*S][768]
// ---------------------------------------------------------------------------
__device__ __align__(128) __nv_bfloat16 g_qhi[(size_t)M_PAD * D_];
__device__ __align__(128) __nv_bfloat16 g_qlo[(size_t)M_PAD * D_];
__device__ __align__(128) __nv_bfloat16 g_khi[(size_t)M_PAD * D_];
__device__ __align__(128) __nv_bfloat16 g_klo[(size_t)M_PAD * D_];
__device__ __align__(128) __nv_bfloat16 g_vhi[(size_t)M_PAD * D_];
__device__ __align__(128) __nv_bfloat16 g_vlo[(size_t)M_PAD * D_];
__device__ __align__(128) __nv_bfloat16 g_xhi[(size_t)M_PAD * D_];
__device__ __align__(128) __nv_bfloat16 g_xlo[(size_t)M_PAD * D_];
__device__ __align__(128) __nv_bfloat16 g_wthi[(size_t)3 * D_ * D_];
__device__ __align__(128) __nv_bfloat16 g_wtlo[(size_t)3 * D_ * D_];

// ---------------------------------------------------------------------------
// Base-ISA PTX helpers
// ---------------------------------------------------------------------------
__device__ __forceinline__ uint32_t smem_u32(const void* p) {
    uint32_t a;
    asm("{ .reg .u64 t; cvta.to.shared.u64 t, %1; cvt.u32.u64 %0, t; }"
        : "=r"(a) : "l"(p));
    return a;
}
__device__ __forceinline__ void cp_async16(uint32_t dst, const void* src) {
    asm volatile("cp.async.cg.shared.global [%0], [%1], 16;\n"
                 :: "r"(dst), "l"(src));
}
__device__ __forceinline__ void ldsm4(uint32_t* r, uint32_t addr) {
    asm volatile("ldmatrix.sync.aligned.m8n8.x4.shared.b16 {%0,%1,%2,%3}, [%4];\n"
                 : "=r"(r[0]), "=r"(r[1]), "=r"(r[2]), "=r"(r[3]) : "r"(addr));
}
__device__ __forceinline__ void ldsm4t(uint32_t* r, uint32_t addr) {
    asm volatile("ldmatrix.sync.aligned.m8n8.x4.trans.shared.b16 {%0,%1,%2,%3}, [%4];\n"
                 : "=r"(r[0]), "=r"(r[1]), "=r"(r[2]), "=r"(r[3]) : "r"(addr));
}
__device__ __forceinline__ void mma16816(float* d, const uint32_t* a,
                                         const uint32_t* b) {
    asm volatile(
        "mma.sync.aligned.m16n8k16.row.col.f32.bf16.bf16.f32 "
        "{%0,%1,%2,%3}, {%4,%5,%6,%7}, {%8,%9}, {%0,%1,%2,%3};\n"
        : "+f"(d[0]), "+f"(d[1]), "+f"(d[2]), "+f"(d[3])
        : "r"(a[0]), "r"(a[1]), "r"(a[2]), "r"(a[3]), "r"(b[0]), "r"(b[1]));
}
__device__ __forceinline__ void split2(float x, float y, uint32_t& hi, uint32_t& lo) {
    __nv_bfloat162 h = __floats2bfloat162_rn(x, y);
    float2 f = __bfloat1622float2(h);
    __nv_bfloat162 l = __floats2bfloat162_rn(x - f.x, y - f.y);
    hi = *(uint32_t*)&h;
    lo = *(uint32_t*)&l;
}

// ---------------------------------------------------------------------------
// Conversion: X -> (hi, lo) bf16, rows >= 8200 zeroed (pad to 8320)
// ---------------------------------------------------------------------------
__global__ __launch_bounds__(256) void convx_kernel(const float* __restrict__ X)
{
    size_t i = ((size_t)blockIdx.x * 256 + threadIdx.x) * 4;
    if (i >= (size_t)M_PAD * D_) return;
    size_t m = i / D_;
    float4 x = (m < M_TOT) ? *(const float4*)&X[i] : make_float4(0.f, 0.f, 0.f, 0.f);
    uint2 uh, ul;
    split2(x.x, x.y, uh.x, ul.x);
    split2(x.z, x.w, uh.y, ul.y);
    *(uint2*)&g_xhi[i] = uh;
    *(uint2*)&g_xlo[i] = ul;
}

// ---------------------------------------------------------------------------
// Conversion: W^T -> (hi, lo) bf16, tiled transpose. Wt[n][k] = W[k][n].
// ---------------------------------------------------------------------------
__global__ __launch_bounds__(256) void convw_kernel(
    const float* __restrict__ Wq, const float* __restrict__ Wk,
    const float* __restrict__ Wv)
{
    __shared__ float t[32][33];
    const float* W = (blockIdx.z == 0) ? Wq : (blockIdx.z == 1) ? Wk : Wv;
    __nv_bfloat16* oh = g_wthi + (size_t)blockIdx.z * D_ * D_;
    __nv_bfloat16* ol = g_wtlo + (size_t)blockIdx.z * D_ * D_;
    int k0 = blockIdx.x * 32, n0 = blockIdx.y * 32;
    for (int i = threadIdx.x; i < 1024; i += 256) {
        int r = i >> 5, c = i & 31;
        t[r][c] = W[(size_t)(k0 + r) * D_ + n0 + c];
    }
    __syncthreads();
    for (int i = threadIdx.x; i < 1024; i += 256) {
        int r = i >> 5, c = i & 31;
        float x = t[c][r];
        __nv_bfloat16 h = __float2bfloat16(x);
        oh[(size_t)(n0 + r) * D_ + k0 + c] = h;
        ol[(size_t)(n0 + r) * D_ + k0 + c] =
            __float2bfloat16(x - __bfloat162float(h));
    }
}

// ---------------------------------------------------------------------------
// mma.sync split-bf16 GEMM (validated R5/R6) — epilogue emits bf16 hi/lo
// for Q (x0.125), K, V.
// ---------------------------------------------------------------------------
#define STAGE_BYTES 65536
#define GEMM_SMEM   (2 * STAGE_BYTES)

__global__ __launch_bounds__(256, 1) void gemm_kernel(
    const float* __restrict__ bq, const float* __restrict__ bk,
    const float* __restrict__ bv)
{
    extern __shared__ __align__(1024) unsigned char smg[];
    uint32_t sb = smem_u32(smg);
    int tid = threadIdx.x, wid = tid >> 5, lid = tid & 31;
    int warp_m = wid & 3, warp_n = wid >> 2;
    int m0 = blockIdx.x * 128;
    int n0 = blockIdx.y * 128;
    int mat = blockIdx.z;

    const __nv_bfloat16* Bhi = g_wthi + (size_t)mat * D_ * D_;
    const __nv_bfloat16* Blo = g_wtlo + (size_t)mat * D_ * D_;
    __nv_bfloat16* ohi = (mat == 0) ? g_qhi : (mat == 1) ? g_khi : g_vhi;
    __nv_bfloat16* olo = (mat == 0) ? g_qlo : (mat == 1) ? g_klo : g_vlo;
    const float* bias = (mat == 0) ? bq : (mat == 1) ? bk : bv;
    const float osc = (mat == 0) ? 0.125f : 1.0f;

    float acc[2][8][4];
#pragma unroll
    for (int f = 0; f < 2; f++)
#pragma unroll
        for (int nf = 0; nf < 8; nf++)
#pragma unroll
            for (int j = 0; j < 4; j++) acc[f][nf][j] = 0.f;

    auto load_stage = [&](int c, int s) {
        int k0 = c * 64;
        uint32_t st = sb + s * STAGE_BYTES;
#pragma unroll
        for (int pass = 0; pass < 8; pass++) {
            int idx = pass * 256 + tid;
            int sp = idx >> 10, rem = idx & 1023;
            int row = rem >> 3, cc = rem & 7;
            const __nv_bfloat16* src =
                (sp ? g_xlo : g_xhi) + (size_t)(m0 + row) * D_ + k0 + cc * 8;
            cp_async16(st + sp * 16384 + row * 128 + ((cc ^ (row & 7)) << 4), src);
        }
#pragma unroll
        for (int pass = 0; pass < 8; pass++) {
            int idx = pass * 256 + tid;
            int sp = idx >> 10, rem = idx & 1023;
            int row = rem >> 3, cc = rem & 7;
            const __nv_bfloat16* src =
                (sp ? Blo : Bhi) + (size_t)(n0 + row) * D_ + k0 + cc * 8;
            cp_async16(st + 32768 + sp * 16384 + row * 128 + ((cc ^ (row & 7)) << 4), src);
        }
        asm volatile("cp.async.commit_group;\n" ::: "memory");
    };

    load_stage(0, 0);

    for (int c = 0; c < 12; c++) {
        int s = c & 1;
        if (c + 1 < 12) {
            load_stage(c + 1, s ^ 1);
            asm volatile("cp.async.wait_group 1;\n" ::: "memory");
        } else {
            asm volatile("cp.async.wait_group 0;\n" ::: "memory");
        }
        __syncthreads();

        uint32_t st  = sb + s * STAGE_BYTES;
        uint32_t bB  = st + 32768;
        int q = lid >> 3, r = lid & 7;

#pragma unroll
        for (int ks = 0; ks < 4; ks++) {
            uint32_t ah[2][4], alr[2][4];
#pragma unroll
            for (int f = 0; f < 2; f++) {
                int mrow = warp_m * 32 + f * 16 + (q & 1) * 8 + r;
                int cc   = ks * 2 + (q >> 1);
                uint32_t addr = st + mrow * 128 + ((cc ^ (mrow & 7)) << 4);
                ldsm4(ah[f], addr);
                ldsm4(alr[f], addr + 16384);
            }
            uint32_t bb[8][2];
#pragma unroll
            for (int g = 0; g < 4; g++) {
                int nrow = warp_n * 64 + g * 16 + (q >> 1) * 8 + r;
                int cc   = ks * 2 + (q & 1);
                uint32_t t[4];
                ldsm4(t, bB + nrow * 128 + ((cc ^ (nrow & 7)) << 4));
                bb[2 * g][0] = t[0]; bb[2 * g][1] = t[1];
                bb[2 * g + 1][0] = t[2]; bb[2 * g + 1][1] = t[3];
            }
#pragma unroll
            for (int f = 0; f < 2; f++)
#pragma unroll
                for (int nf = 0; nf < 8; nf++) {
                    mma16816(acc[f][nf], ah[f], bb[nf]);
                    mma16816(acc[f][nf], alr[f], bb[nf]);
                }
#pragma unroll
            for (int g = 0; g < 4; g++) {
                int nrow = warp_n * 64 + g * 16 + (q >> 1) * 8 + r;
                int cc   = ks * 2 + (q & 1);
                uint32_t t[4];
                ldsm4(t, bB + 16384 + nrow * 128 + ((cc ^ (nrow & 7)) << 4));
                bb[2 * g][0] = t[0]; bb[2 * g][1] = t[1];
                bb[2 * g + 1][0] = t[2]; bb[2 * g + 1][1] = t[3];
            }
#pragma unroll
            for (int f = 0; f < 2; f++)
#pragma unroll
                for (int nf = 0; nf < 8; nf++)
                    mma16816(acc[f][nf], ah[f], bb[nf]);
        }
        __syncthreads();
    }

    // ---- epilogue: split-bf16 hi/lo + bias (+0.125 scale for Q) ----
    int g2 = lid >> 2, tg = lid & 3;
    int mbase = m0 + warp_m * 32;
    int nbase = n0 + warp_n * 64;
#pragma unroll
    for (int f = 0; f < 2; f++) {
#pragma unroll
        for (int nf = 0; nf < 8; nf++) {
            int n = nbase + nf * 8 + tg * 2;
            float b0 = bias[n], b1 = bias[n + 1];
            int m = mbase + f * 16 + g2;
            if (m < M_TOT) {
                uint32_t h, l;
                split2((acc[f][nf][0] + b0) * osc, (acc[f][nf][1] + b1) * osc, h, l);
                *(uint32_t*)&ohi[(size_t)m * D_ + n] = h;
                *(uint32_t*)&olo[(size_t)m * D_ + n] = l;
            }
            if (m + 8 < M_TOT) {
                uint32_t h, l;
                split2((acc[f][nf][2] + b0) * osc, (acc[f][nf][3] + b1) * osc, h, l);
                *(uint32_t*)&ohi[(size_t)(m + 8) * D_ + n] = h;
                *(uint32_t*)&olo[(size_t)(m + 8) * D_ + n] = l;
            }
        }
    }
}

// ---------------------------------------------------------------------------
// Tensor-core flash attention. Block = (64 q, b, h), 4 warps; warp owns 16 q.
// 128-thread CTAs so TWO CTAs co-reside per SM (regs ~194 -> 2x128x200 < 64K),
// giving two independent phase streams (softmax of one CTA overlaps MMAs of
// the other). Split-bf16 3-MMA for S=Q'K^T and O=PV; online softmax in frags.
// smem: 2 x 32KB KV stages (Khi|Klo|Vhi|Vlo, 8KB each); Q staged in stage-0
// region once (hi 8KB + lo 8KB), frags extracted, then region reused for KV.
// ---------------------------------------------------------------------------
#define QT   64
#define NKT  17
#define ATT_SMEM 65536

__global__ __launch_bounds__(128, 2) void attn_kernel(
    const float* __restrict__ rel_bias, float* __restrict__ out)
{
    extern __shared__ __align__(1024) unsigned char sma[];
    uint32_t sb = smem_u32(sma);
    int tid = threadIdx.x, wid = tid >> 5, lid = tid & 31;
    int qq = lid >> 3, r = lid & 7;       // ldmatrix lane decomposition
    int g  = lid >> 2, t = lid & 3;       // mma accum lane decomposition
    int q0 = blockIdx.x * QT;
    int b  = blockIdx.y;
    int h  = blockIdx.z;

    const __nv_bfloat16* arrp[4] = {g_khi, g_klo, g_vhi, g_vlo};

    auto load_q = [&]() {
#pragma unroll
        for (int p = 0; p < 8; p++) {
            int idx = p * 128 + tid;                 // 1024 chunks
            int sp = idx >> 9, rem = idx & 511;
            int row = rem >> 3, cc = rem & 7;
            int gq = q0 + row; if (gq > S_ - 1) gq = S_ - 1;
            const __nv_bfloat16* src = (sp ? g_qlo : g_qhi)
                + (size_t)(b * S_ + gq) * D_ + h * HD_ + cc * 8;
            cp_async16(sb + sp * 8192 + row * 128 + ((cc ^ (row & 7)) << 4), src);
        }
        asm volatile("cp.async.commit_group;\n" ::: "memory");
    };
    auto load_kv = [&](int kt, int s) {
#pragma unroll
        for (int p = 0; p < 16; p++) {
            int idx = p * 128 + tid;                 // 2048 chunks
            int a = idx >> 9, rem = idx & 511;
            int row = rem >> 3, cc = rem & 7;
            int gk = kt * 64 + row; if (gk > S_ - 1) gk = S_ - 1;
            const __nv_bfloat16* src = arrp[a]
                + (size_t)(b * S_ + gk) * D_ + h * HD_ + cc * 8;
            cp_async16(sb + s * 32768 + a * 8192 + row * 128 + ((cc ^ (row & 7)) << 4), src);
        }
        asm volatile("cp.async.commit_group;\n" ::: "memory");
    };

    load_q();
    load_kv(0, 1);
    asm volatile("cp.async.wait_group 1;\n" ::: "memory");
    __syncthreads();

    // Extract Q A-fragments (hi+lo) to registers.
    uint32_t qh[4][4], qlr[4][4];
#pragma unroll
    for (int ks = 0; ks < 4; ks++) {
        int mrow = wid * 16 + (qq & 1) * 8 + r;
        int cc = ks * 2 + (qq >> 1);
        uint32_t addr = sb + mrow * 128 + ((cc ^ (mrow & 7)) << 4);
        ldsm4(qh[ks], addr);
        ldsm4(qlr[ks], addr + 8192);
    }
    __syncthreads();    // stage-0 region now reusable for KV

    float o[8][4];
#pragma unroll
    for (int nt = 0; nt < 8; nt++)
#pragma unroll
        for (int j = 0; j < 4; j++) o[nt][j] = 0.f;
    float rm0 = -1e30f, rm1 = -1e30f, rl0 = 0.f, rl1 = 0.f;

    int rq0 = q0 + wid * 16 + g;
    int rq1 = rq0 + 8;
    const float* bp0 = rel_bias + ((size_t)h * S_ + min(rq0, S_ - 1)) * S_;
    const float* bp1 = rel_bias + ((size_t)h * S_ + min(rq1, S_ - 1)) * S_;

    for (int it = 0; it < NKT; it++) {
        int s = (it + 1) & 1;
        __syncthreads();                       // prior compute done -> s^1 reusable
        if (it + 1 < NKT) {
            load_kv(it + 1, s ^ 1);
            asm volatile("cp.async.wait_group 1;\n" ::: "memory");
        } else {
            asm volatile("cp.async.wait_group 0;\n" ::: "memory");
        }
        __syncthreads();                       // stage s visible to all

        uint32_t kb = sb + s * 32768;
        float sc[8][4];
#pragma unroll
        for (int nt = 0; nt < 8; nt++)
#pragma unroll
            for (int j = 0; j < 4; j++) sc[nt][j] = 0.f;

        // ---- S = Q' K^T (3-MMA split) ----
#pragma unroll
        for (int ks = 0; ks < 4; ks++) {
            uint32_t bf[8][2];
#pragma unroll
            for (int gg = 0; gg < 4; gg++) {
                int nrow = gg * 16 + (qq >> 1) * 8 + r;
                int cc = ks * 2 + (qq & 1);
                uint32_t tt[4];
                ldsm4(tt, kb + nrow * 128 + ((cc ^ (nrow & 7)) << 4));
                bf[2 * gg][0] = tt[0]; bf[2 * gg][1] = tt[1];
                bf[2 * gg + 1][0] = tt[2]; bf[2 * gg + 1][1] = tt[3];
            }
#pragma unroll
            for (int nt = 0; nt < 8; nt++) {
                mma16816(sc[nt], qh[ks], bf[nt]);
                mma16816(sc[nt], qlr[ks], bf[nt]);
            }
#pragma unroll
            for (int gg = 0; gg < 4; gg++) {
                int nrow = gg * 16 + (qq >> 1) * 8 + r;
                int cc = ks * 2 + (qq & 1);
                uint32_t tt[4];
                ldsm4(tt, kb + 8192 + nrow * 128 + ((cc ^ (nrow & 7)) << 4));
                bf[2 * gg][0] = tt[0]; bf[2 * gg][1] = tt[1];
                bf[2 * gg + 1][0] = tt[2]; bf[2 * gg + 1][1] = tt[3];
            }
#pragma unroll
            for (int nt = 0; nt < 8; nt++)
                mma16816(sc[nt], qh[ks], bf[nt]);
        }

        // ---- bias + mask + online softmax ----
        int kbase = it * 64;
        float nx0 = rm0, nx1 = rm1;
#pragma unroll
        for (int nt = 0; nt < 8; nt++) {
            int kc = kbase + nt * 8 + 2 * t;
            bool v0 = kc < S_, v1 = (kc + 1) < S_;
            float b00 = v0 ? bp0[kc] : 0.f;
            float b01 = v1 ? bp0[kc + 1] : 0.f;
            float b10 = v0 ? bp1[kc] : 0.f;
            float b11 = v1 ? bp1[kc + 1] : 0.f;
            sc[nt][0] = v0 ? sc[nt][0] + b00 : -1e30f;
            sc[nt][1] = v1 ? sc[nt][1] + b01 : -1e30f;
            sc[nt][2] = v0 ? sc[nt][2] + b10 : -1e30f;
            sc[nt][3] = v1 ? sc[nt][3] + b11 : -1e30f;
            nx0 = fmaxf(nx0, fmaxf(sc[nt][0], sc[nt][1]));
            nx1 = fmaxf(nx1, fmaxf(sc[nt][2], sc[nt][3]));
        }
        nx0 = fmaxf(nx0, __shfl_xor_sync(0xffffffffu, nx0, 1));
        nx0 = fmaxf(nx0, __shfl_xor_sync(0xffffffffu, nx0, 2));
        nx1 = fmaxf(nx1, __shfl_xor_sync(0xffffffffu, nx1, 1));
        nx1 = fmaxf(nx1, __shfl_xor_sync(0xffffffffu, nx1, 2));
        float a0 = __expf(rm0 - nx0), a1 = __expf(rm1 - nx1);
        rm0 = nx0; rm1 = nx1;
        float s0 = 0.f, s1 = 0.f;
#pragma unroll
        for (int nt = 0; nt < 8; nt++) {
            sc[nt][0] = __expf(sc[nt][0] - nx0);
            sc[nt][1] = __expf(sc[nt][1] - nx0);
            sc[nt][2] = __expf(sc[nt][2] - nx1);
            sc[nt][3] = __expf(sc[nt][3] - nx1);
            s0 += sc[nt][0] + sc[nt][1];
            s1 += sc[nt][2] + sc[nt][3];
        }
        s0 += __shfl_xor_sync(0xffffffffu, s0, 1);
        s0 += __shfl_xor_sync(0xffffffffu, s0, 2);
        s1 += __shfl_xor_sync(0xffffffffu, s1, 1);
        s1 += __shfl_xor_sync(0xffffffffu, s1, 2);
        rl0 = rl0 * a0 + s0;
        rl1 = rl1 * a1 + s1;
#pragma unroll
        for (int nt = 0; nt < 8; nt++) {
            o[nt][0] *= a0; o[nt][1] *= a0; o[nt][2] *= a1; o[nt][3] *= a1;
        }

        // ---- O += P V (3-MMA split; P frags built in registers) ----
        uint32_t vb = kb + 16384;
#pragma unroll
        for (int ks = 0; ks < 4; ks++) {
            uint32_t ah[4], al[4];
            split2(sc[2 * ks][0],     sc[2 * ks][1],     ah[0], al[0]);
            split2(sc[2 * ks][2],     sc[2 * ks][3],     ah[1], al[1]);
            split2(sc[2 * ks + 1][0], sc[2 * ks + 1][1], ah[2], al[2]);
            split2(sc[2 * ks + 1][2], sc[2 * ks + 1][3], ah[3], al[3]);

            uint32_t bf[8][2];
#pragma unroll
            for (int dp = 0; dp < 4; dp++) {
                int row = ks * 16 + (qq & 1) * 8 + r;
                int cc = dp * 2 + (qq >> 1);
                uint32_t tt[4];
                ldsm4t(tt, vb + row * 128 + ((cc ^ (row & 7)) << 4));
                bf[2 * dp][0] = tt[0]; bf[2 * dp][1] = tt[1];
                bf[2 * dp + 1][0] = tt[2]; bf[2 * dp + 1][1] = tt[3];
            }
#pragma unroll
            for (int nt = 0; nt < 8; nt++) {
                mma16816(o[nt], ah, bf[nt]);
                mma16816(o[nt], al, bf[nt]);
            }
#pragma unroll
            for (int dp = 0; dp < 4; dp++) {
                int row = ks * 16 + (qq & 1) * 8 + r;
                int cc = dp * 2 + (qq >> 1);
                uint32_t tt[4];
                ldsm4t(tt, vb + 8192 + row * 128 + ((cc ^ (row & 7)) << 4));
                bf[2 * dp][0] = tt[0]; bf[2 * dp][1] = tt[1];
                bf[2 * dp + 1][0] = tt[2]; bf[2 * dp + 1][1] = tt[3];
            }
#pragma unroll
            for (int nt = 0; nt < 8; nt++)
                mma16816(o[nt], ah, bf[nt]);
        }
    }

    // ---- finalize + store ----
    float i0 = 1.f / rl0, i1 = 1.f / rl1;
#pragma unroll
    for (int nt = 0; nt < 8; nt++) {
        int dc = h * HD_ + nt * 8 + 2 * t;
        if (rq0 < S_)
            *(float2*)&out[((size_t)b * S_ + rq0) * D_ + dc] =
                make_float2(o[nt][0] * i0, o[nt][1] * i0);
        if (rq1 < S_)
            *(float2*)&out[((size_t)b * S_ + rq1) * D_ + dc] =
                make_float2(o[nt][2] * i1, o[nt][3] * i1);
    }
}

// ---------------------------------------------------------------------------
extern "C" void kernel_launch(void* const* d_in, const int* in_sizes, int n_in,
                              void* d_out, int out_size)
{
    const float* hidden = (const float*)d_in[0];
    const float* bias   = (const float*)d_in[1];
    const float* Wq     = (const float*)d_in[2];
    const float* bq     = (const float*)d_in[3];
    const float* Wk     = (const float*)d_in[4];
    const float* bk     = (const float*)d_in[5];
    const float* Wv     = (const float*)d_in[6];
    const float* bv     = (const float*)d_in[7];
    float* out = (float*)d_out;

    cudaFuncSetAttribute(gemm_kernel,
                         cudaFuncAttributeMaxDynamicSharedMemorySize, GEMM_SMEM);
    cudaFuncSetAttribute(attn_kernel,
                         cudaFuncAttributeMaxDynamicSharedMemorySize, ATT_SMEM);

    convx_kernel<<<(M_PAD * D_ / 4 + 255) / 256, 256>>>(hidden);
    convw_kernel<<<dim3(24, 24, 3), 256>>>(Wq, Wk, Wv);
    gemm_kernel<<<dim3(65, 6, 3), 256, GEMM_SMEM>>>(bq, bk, bv);

    dim3 g2((S_ + QT - 1) / QT, B_, H_);   // (17, 8, 12)
    attn_kernel<<<g2, 128, ATT_SMEM>>>(bias, out);
}

// round 11
// speedup vs baseline: 3.2790x; 1.2394x over previous
#include <cuda_runtime.h>
#include <cuda_bf16.h>
#include <cstdint>

#define B_    8
#define S_    1025
#define D_    768
#define H_    12
#define HD_   64
#define M_TOT (B_ * S_)       // 8200
#define M_PAD 8320            // 65 * 128
#define SPAD  1028            // bias row pitch (floats), 16B-aligned

// ---------------------------------------------------------------------------
// Device scratch
// ---------------------------------------------------------------------------
__device__ __align__(128) __nv_bfloat16 g_qhi[(size_t)M_PAD * D_];
__device__ __align__(128) __nv_bfloat16 g_qlo[(size_t)M_PAD * D_];
__device__ __align__(128) __nv_bfloat16 g_khi[(size_t)M_PAD * D_];
__device__ __align__(128) __nv_bfloat16 g_klo[(size_t)M_PAD * D_];
__device__ __align__(128) __nv_bfloat16 g_vhi[(size_t)M_PAD * D_];
__device__ __align__(128) __nv_bfloat16 g_vlo[(size_t)M_PAD * D_];
__device__ __align__(128) __nv_bfloat16 g_xhi[(size_t)M_PAD * D_];
__device__ __align__(128) __nv_bfloat16 g_xlo[(size_t)M_PAD * D_];
__device__ __align__(128) __nv_bfloat16 g_wthi[(size_t)3 * D_ * D_];
__device__ __align__(128) __nv_bfloat16 g_wtlo[(size_t)3 * D_ * D_];
__device__ __align__(128) float g_biasp[(size_t)H_ * S_ * SPAD];   // padded rel_bias

// ---------------------------------------------------------------------------
// Base-ISA PTX helpers
// ---------------------------------------------------------------------------
__device__ __forceinline__ uint32_t smem_u32(const void* p) {
    uint32_t a;
    asm("{ .reg .u64 t; cvta.to.shared.u64 t, %1; cvt.u32.u64 %0, t; }"
        : "=r"(a) : "l"(p));
    return a;
}
__device__ __forceinline__ void cp_async16(uint32_t dst, const void* src) {
    asm volatile("cp.async.cg.shared.global [%0], [%1], 16;\n"
                 :: "r"(dst), "l"(src));
}
__device__ __forceinline__ void ldsm4(uint32_t* r, uint32_t addr) {
    asm volatile("ldmatrix.sync.aligned.m8n8.x4.shared.b16 {%0,%1,%2,%3}, [%4];\n"
                 : "=r"(r[0]), "=r"(r[1]), "=r"(r[2]), "=r"(r[3]) : "r"(addr));
}
__device__ __forceinline__ void ldsm4t(uint32_t* r, uint32_t addr) {
    asm volatile("ldmatrix.sync.aligned.m8n8.x4.trans.shared.b16 {%0,%1,%2,%3}, [%4];\n"
                 : "=r"(r[0]), "=r"(r[1]), "=r"(r[2]), "=r"(r[3]) : "r"(addr));
}
__device__ __forceinline__ void mma16816(float* d, const uint32_t* a,
                                         const uint32_t* b) {
    asm volatile(
        "mma.sync.aligned.m16n8k16.row.col.f32.bf16.bf16.f32 "
        "{%0,%1,%2,%3}, {%4,%5,%6,%7}, {%8,%9}, {%0,%1,%2,%3};\n"
        : "+f"(d[0]), "+f"(d[1]), "+f"(d[2]), "+f"(d[3])
        : "r"(a[0]), "r"(a[1]), "r"(a[2]), "r"(a[3]), "r"(b[0]), "r"(b[1]));
}
__device__ __forceinline__ void split2(float x, float y, uint32_t& hi, uint32_t& lo) {
    __nv_bfloat162 h = __floats2bfloat162_rn(x, y);
    float2 f = __bfloat1622float2(h);
    __nv_bfloat162 l = __floats2bfloat162_rn(x - f.x, y - f.y);
    hi = *(uint32_t*)&h;
    lo = *(uint32_t*)&l;
}

// ---------------------------------------------------------------------------
// Conversion: X -> (hi, lo) bf16, rows >= 8200 zeroed (pad to 8320)
// ---------------------------------------------------------------------------
__global__ __launch_bounds__(256) void convx_kernel(const float* __restrict__ X)
{
    size_t i = ((size_t)blockIdx.x * 256 + threadIdx.x) * 4;
    if (i >= (size_t)M_PAD * D_) return;
    size_t m = i / D_;
    float4 x = (m < M_TOT) ? *(const float4*)&X[i] : make_float4(0.f, 0.f, 0.f, 0.f);
    uint2 uh, ul;
    split2(x.x, x.y, uh.x, ul.x);
    split2(x.z, x.w, uh.y, ul.y);
    *(uint2*)&g_xhi[i] = uh;
    *(uint2*)&g_xlo[i] = ul;
}

// ---------------------------------------------------------------------------
// Conversion: W^T -> (hi, lo) bf16, tiled transpose. Wt[n][k] = W[k][n].
// ---------------------------------------------------------------------------
__global__ __launch_bounds__(256) void convw_kernel(
    const float* __restrict__ Wq, const float* __restrict__ Wk,
    const float* __restrict__ Wv)
{
    __shared__ float t[32][33];
    const float* W = (blockIdx.z == 0) ? Wq : (blockIdx.z == 1) ? Wk : Wv;
    __nv_bfloat16* oh = g_wthi + (size_t)blockIdx.z * D_ * D_;
    __nv_bfloat16* ol = g_wtlo + (size_t)blockIdx.z * D_ * D_;
    int k0 = blockIdx.x * 32, n0 = blockIdx.y * 32;
    for (int i = threadIdx.x; i < 1024; i += 256) {
        int r = i >> 5, c = i & 31;
        t[r][c] = W[(size_t)(k0 + r) * D_ + n0 + c];
    }
    __syncthreads();
    for (int i = threadIdx.x; i < 1024; i += 256) {
        int r = i >> 5, c = i & 31;
        float x = t[c][r];
        __nv_bfloat16 h = __float2bfloat16(x);
        oh[(size_t)(n0 + r) * D_ + k0 + c] = h;
        ol[(size_t)(n0 + r) * D_ + k0 + c] =
            __float2bfloat16(x - __bfloat162float(h));
    }
}

// ---------------------------------------------------------------------------
// Repack rel_bias [H][S][S] -> g_biasp [H][S][SPAD] (rows 16B-aligned).
// ---------------------------------------------------------------------------
__global__ __launch_bounds__(256) void convb_kernel(const float* __restrict__ rb)
{
    size_t i = (size_t)blockIdx.x * 256 + threadIdx.x;
    const size_t tot = (size_t)H_ * S_ * S_;
    if (i >= tot) return;
    size_t row = i / S_;
    int col = (int)(i - row * S_);
    g_biasp[row * SPAD + col] = rb[i];
}

// ---------------------------------------------------------------------------
// mma.sync split-bf16 GEMM (validated R5/R6) — epilogue emits bf16 hi/lo
// for Q (x0.125), K, V.
// ---------------------------------------------------------------------------
#define STAGE_BYTES 65536
#define GEMM_SMEM   (2 * STAGE_BYTES)

__global__ __launch_bounds__(256, 1) void gemm_kernel(
    const float* __restrict__ bq, const float* __restrict__ bk,
    const float* __restrict__ bv)
{
    extern __shared__ __align__(1024) unsigned char smg[];
    uint32_t sb = smem_u32(smg);
    int tid = threadIdx.x, wid = tid >> 5, lid = tid & 31;
    int warp_m = wid & 3, warp_n = wid >> 2;
    int m0 = blockIdx.x * 128;
    int n0 = blockIdx.y * 128;
    int mat = blockIdx.z;

    const __nv_bfloat16* Bhi = g_wthi + (size_t)mat * D_ * D_;
    const __nv_bfloat16* Blo = g_wtlo + (size_t)mat * D_ * D_;
    __nv_bfloat16* ohi = (mat == 0) ? g_qhi : (mat == 1) ? g_khi : g_vhi;
    __nv_bfloat16* olo = (mat == 0) ? g_qlo : (mat == 1) ? g_klo : g_vlo;
    const float* bias = (mat == 0) ? bq : (mat == 1) ? bk : bv;
    const float osc = (mat == 0) ? 0.125f : 1.0f;

    float acc[2][8][4];
#pragma unroll
    for (int f = 0; f < 2; f++)
#pragma unroll
        for (int nf = 0; nf < 8; nf++)
#pragma unroll
            for (int j = 0; j < 4; j++) acc[f][nf][j] = 0.f;

    auto load_stage = [&](int c, int s) {
        int k0 = c * 64;
        uint32_t st = sb + s * STAGE_BYTES;
#pragma unroll
        for (int pass = 0; pass < 8; pass++) {
            int idx = pass * 256 + tid;
            int sp = idx >> 10, rem = idx & 1023;
            int row = rem >> 3, cc = rem & 7;
            const __nv_bfloat16* src =
                (sp ? g_xlo : g_xhi) + (size_t)(m0 + row) * D_ + k0 + cc * 8;
            cp_async16(st + sp * 16384 + row * 128 + ((cc ^ (row & 7)) << 4), src);
        }
#pragma unroll
        for (int pass = 0; pass < 8; pass++) {
            int idx = pass * 256 + tid;
            int sp = idx >> 10, rem = idx & 1023;
            int row = rem >> 3, cc = rem & 7;
            const __nv_bfloat16* src =
                (sp ? Blo : Bhi) + (size_t)(n0 + row) * D_ + k0 + cc * 8;
            cp_async16(st + 32768 + sp * 16384 + row * 128 + ((cc ^ (row & 7)) << 4), src);
        }
        asm volatile("cp.async.commit_group;\n" ::: "memory");
    };

    load_stage(0, 0);

    for (int c = 0; c < 12; c++) {
        int s = c & 1;
        if (c + 1 < 12) {
            load_stage(c + 1, s ^ 1);
            asm volatile("cp.async.wait_group 1;\n" ::: "memory");
        } else {
            asm volatile("cp.async.wait_group 0;\n" ::: "memory");
        }
        __syncthreads();

        uint32_t st  = sb + s * STAGE_BYTES;
        uint32_t bB  = st + 32768;
        int q = lid >> 3, r = lid & 7;

#pragma unroll
        for (int ks = 0; ks < 4; ks++) {
            uint32_t ah[2][4], alr[2][4];
#pragma unroll
            for (int f = 0; f < 2; f++) {
                int mrow = warp_m * 32 + f * 16 + (q & 1) * 8 + r;
                int cc   = ks * 2 + (q >> 1);
                uint32_t addr = st + mrow * 128 + ((cc ^ (mrow & 7)) << 4);
                ldsm4(ah[f], addr);
                ldsm4(alr[f], addr + 16384);
            }
            uint32_t bb[8][2];
#pragma unroll
            for (int g = 0; g < 4; g++) {
                int nrow = warp_n * 64 + g * 16 + (q >> 1) * 8 + r;
                int cc   = ks * 2 + (q & 1);
                uint32_t t[4];
                ldsm4(t, bB + nrow * 128 + ((cc ^ (nrow & 7)) << 4));
                bb[2 * g][0] = t[0]; bb[2 * g][1] = t[1];
                bb[2 * g + 1][0] = t[2]; bb[2 * g + 1][1] = t[3];
            }
#pragma unroll
            for (int f = 0; f < 2; f++)
#pragma unroll
                for (int nf = 0; nf < 8; nf++) {
                    mma16816(acc[f][nf], ah[f], bb[nf]);
                    mma16816(acc[f][nf], alr[f], bb[nf]);
                }
#pragma unroll
            for (int g = 0; g < 4; g++) {
                int nrow = warp_n * 64 + g * 16 + (q >> 1) * 8 + r;
                int cc   = ks * 2 + (q & 1);
                uint32_t t[4];
                ldsm4(t, bB + 16384 + nrow * 128 + ((cc ^ (nrow & 7)) << 4));
                bb[2 * g][0] = t[0]; bb[2 * g][1] = t[1];
                bb[2 * g + 1][0] = t[2]; bb[2 * g + 1][1] = t[3];
            }
#pragma unroll
            for (int f = 0; f < 2; f++)
#pragma unroll
                for (int nf = 0; nf < 8; nf++)
                    mma16816(acc[f][nf], ah[f], bb[nf]);
        }
        __syncthreads();
    }

    // ---- epilogue: split-bf16 hi/lo + bias (+0.125 scale for Q) ----
    int g2 = lid >> 2, tg = lid & 3;
    int mbase = m0 + warp_m * 32;
    int nbase = n0 + warp_n * 64;
#pragma unroll
    for (int f = 0; f < 2; f++) {
#pragma unroll
        for (int nf = 0; nf < 8; nf++) {
            int n = nbase + nf * 8 + tg * 2;
            float b0 = bias[n], b1 = bias[n + 1];
            int m = mbase + f * 16 + g2;
            if (m < M_TOT) {
                uint32_t h, l;
                split2((acc[f][nf][0] + b0) * osc, (acc[f][nf][1] + b1) * osc, h, l);
                *(uint32_t*)&ohi[(size_t)m * D_ + n] = h;
                *(uint32_t*)&olo[(size_t)m * D_ + n] = l;
            }
            if (m + 8 < M_TOT) {
                uint32_t h, l;
                split2((acc[f][nf][2] + b0) * osc, (acc[f][nf][3] + b1) * osc, h, l);
                *(uint32_t*)&ohi[(size_t)(m + 8) * D_ + n] = h;
                *(uint32_t*)&olo[(size_t)(m + 8) * D_ + n] = l;
            }
        }
    }
}

// ---------------------------------------------------------------------------
// Tensor-core flash attention. Block = (64 q, b, h), 4 warps; warp owns 16 q.
// 128-thread CTAs, 2 CTAs/SM. Split-bf16 3-MMA for S=Q'K^T and O=PV.
// rel_bias tile (64q x 64k fp32, pitch 68) prefetched per stage via cp.async
// from the PADDED bias buffer (rows 16B-aligned) -> softmax reads smem.
// Stage layout: Khi|Klo|Vhi|Vlo (8KB each) | bias (64*272B).
// ---------------------------------------------------------------------------
#define QT   64
#define NKT  17
#define BIAS_OFF 32768
#define KVST (32768 + 64 * 272)          // 50176 per stage
#define ATT_SMEM (2 * KVST)              // 100352

__global__ __launch_bounds__(128, 2) void attn_kernel(float* __restrict__ out)
{
    extern __shared__ __align__(1024) unsigned char sma[];
    uint32_t sb = smem_u32(sma);
    int tid = threadIdx.x, wid = tid >> 5, lid = tid & 31;
    int qq = lid >> 3, r = lid & 7;       // ldmatrix lane decomposition
    int g  = lid >> 2, t = lid & 3;       // mma accum lane decomposition
    int q0 = blockIdx.x * QT;
    int b  = blockIdx.y;
    int h  = blockIdx.z;

    const __nv_bfloat16* arrp[4] = {g_khi, g_klo, g_vhi, g_vlo};

    auto load_q = [&]() {
#pragma unroll
        for (int p = 0; p < 8; p++) {
            int idx = p * 128 + tid;                 // 1024 chunks
            int sp = idx >> 9, rem = idx & 511;
            int row = rem >> 3, cc = rem & 7;
            int gq = q0 + row; if (gq > S_ - 1) gq = S_ - 1;
            const __nv_bfloat16* src = (sp ? g_qlo : g_qhi)
                + (size_t)(b * S_ + gq) * D_ + h * HD_ + cc * 8;
            cp_async16(sb + sp * 8192 + row * 128 + ((cc ^ (row & 7)) << 4), src);
        }
        asm volatile("cp.async.commit_group;\n" ::: "memory");
    };
    auto load_kv = [&](int kt, int s) {
#pragma unroll
        for (int p = 0; p < 16; p++) {
            int idx = p * 128 + tid;                 // 2048 chunks
            int a = idx >> 9, rem = idx & 511;
            int row = rem >> 3, cc = rem & 7;
            int gk = kt * 64 + row; if (gk > S_ - 1) gk = S_ - 1;
            const __nv_bfloat16* src = arrp[a]
                + (size_t)(b * S_ + gk) * D_ + h * HD_ + cc * 8;
            cp_async16(sb + s * KVST + a * 8192 + row * 128 + ((cc ^ (row & 7)) << 4), src);
        }
        // bias tile: 64 q-rows x 64 keys fp32 from padded buffer (16B rows)
#pragma unroll
        for (int p = 0; p < 8; p++) {
            int idx = p * 128 + tid;                 // 1024 chunks
            int row = idx >> 4, cc = idx & 15;
            int gq = q0 + row; if (gq > S_ - 1) gq = S_ - 1;
            int kc = kt * 64 + cc * 4;               // kc+4 <= 1088 < SPAD rows OK
            const float* src = g_biasp + ((size_t)h * S_ + gq) * SPAD + kc;
            cp_async16(sb + s * KVST + BIAS_OFF + row * 272 + cc * 16, src);
        }
        asm volatile("cp.async.commit_group;\n" ::: "memory");
    };

    load_q();
    load_kv(0, 1);
    asm volatile("cp.async.wait_group 1;\n" ::: "memory");
    __syncthreads();

    // Extract Q A-fragments (hi+lo) to registers.
    uint32_t qh[4][4], qlr[4][4];
#pragma unroll
    for (int ks = 0; ks < 4; ks++) {
        int mrow = wid * 16 + (qq & 1) * 8 + r;
        int cc = ks * 2 + (qq >> 1);
        uint32_t addr = sb + mrow * 128 + ((cc ^ (mrow & 7)) << 4);
        ldsm4(qh[ks], addr);
        ldsm4(qlr[ks], addr + 8192);
    }
    __syncthreads();    // stage-0 region now reusable for KV

    float o[8][4];
#pragma unroll
    for (int nt = 0; nt < 8; nt++)
#pragma unroll
        for (int j = 0; j < 4; j++) o[nt][j] = 0.f;
    float rm0 = -1e30f, rm1 = -1e30f, rl0 = 0.f, rl1 = 0.f;

    int rq0 = q0 + wid * 16 + g;
    int rq1 = rq0 + 8;

    for (int it = 0; it < NKT; it++) {
        int s = (it + 1) & 1;
        __syncthreads();                       // prior compute done -> s^1 reusable
        if (it + 1 < NKT) {
            load_kv(it + 1, s ^ 1);
            asm volatile("cp.async.wait_group 1;\n" ::: "memory");
        } else {
            asm volatile("cp.async.wait_group 0;\n" ::: "memory");
        }
        __syncthreads();                       // stage s visible to all

        uint32_t kb = sb + s * KVST;
        float sc[8][4];
#pragma unroll
        for (int nt = 0; nt < 8; nt++)
#pragma unroll
            for (int j = 0; j < 4; j++) sc[nt][j] = 0.f;

        // ---- S = Q' K^T (3-MMA split) ----
#pragma unroll
        for (int ks = 0; ks < 4; ks++) {
            uint32_t bf[8][2];
#pragma unroll
            for (int gg = 0; gg < 4; gg++) {
                int nrow = gg * 16 + (qq >> 1) * 8 + r;
                int cc = ks * 2 + (qq & 1);
                uint32_t tt[4];
                ldsm4(tt, kb + nrow * 128 + ((cc ^ (nrow & 7)) << 4));
                bf[2 * gg][0] = tt[0]; bf[2 * gg][1] = tt[1];
                bf[2 * gg + 1][0] = tt[2]; bf[2 * gg + 1][1] = tt[3];
            }
#pragma unroll
            for (int nt = 0; nt < 8; nt++) {
                mma16816(sc[nt], qh[ks], bf[nt]);
                mma16816(sc[nt], qlr[ks], bf[nt]);
            }
#pragma unroll
            for (int gg = 0; gg < 4; gg++) {
                int nrow = gg * 16 + (qq >> 1) * 8 + r;
                int cc = ks * 2 + (qq & 1);
                uint32_t tt[4];
                ldsm4(tt, kb + 8192 + nrow * 128 + ((cc ^ (nrow & 7)) << 4));
                bf[2 * gg][0] = tt[0]; bf[2 * gg][1] = tt[1];
                bf[2 * gg + 1][0] = tt[2]; bf[2 * gg + 1][1] = tt[3];
            }
#pragma unroll
            for (int nt = 0; nt < 8; nt++)
                mma16816(sc[nt], qh[ks], bf[nt]);
        }

        // ---- bias (from smem) + mask + online softmax ----
        const float* bsm = (const float*)(sma + s * KVST + BIAS_OFF);
        const float* br0 = bsm + (wid * 16 + g) * 68 + 2 * t;
        const float* br1 = br0 + 8 * 68;
        int kbase = it * 64;
        float nx0 = rm0, nx1 = rm1;
#pragma unroll
        for (int nt = 0; nt < 8; nt++) {
            int kc = kbase + nt * 8 + 2 * t;
            bool v0 = kc < S_, v1 = (kc + 1) < S_;
            float2 b0 = *(const float2*)(br0 + nt * 8);
            float2 b1 = *(const float2*)(br1 + nt * 8);
            sc[nt][0] = v0 ? sc[nt][0] + b0.x : -1e30f;
            sc[nt][1] = v1 ? sc[nt][1] + b0.y : -1e30f;
            sc[nt][2] = v0 ? sc[nt][2] + b1.x : -1e30f;
            sc[nt][3] = v1 ? sc[nt][3] + b1.y : -1e30f;
            nx0 = fmaxf(nx0, fmaxf(sc[nt][0], sc[nt][1]));
            nx1 = fmaxf(nx1, fmaxf(sc[nt][2], sc[nt][3]));
        }
        nx0 = fmaxf(nx0, __shfl_xor_sync(0xffffffffu, nx0, 1));
        nx0 = fmaxf(nx0, __shfl_xor_sync(0xffffffffu, nx0, 2));
        nx1 = fmaxf(nx1, __shfl_xor_sync(0xffffffffu, nx1, 1));
        nx1 = fmaxf(nx1, __shfl_xor_sync(0xffffffffu, nx1, 2));
        float a0 = __expf(rm0 - nx0), a1 = __expf(rm1 - nx1);
        rm0 = nx0; rm1 = nx1;
        float s0 = 0.f, s1 = 0.f;
#pragma unroll
        for (int nt = 0; nt < 8; nt++) {
            sc[nt][0] = __expf(sc[nt][0] - nx0);
            sc[nt][1] = __expf(sc[nt][1] - nx0);
            sc[nt][2] = __expf(sc[nt][2] - nx1);
            sc[nt][3] = __expf(sc[nt][3] - nx1);
            s0 += sc[nt][0] + sc[nt][1];
            s1 += sc[nt][2] + sc[nt][3];
        }
        s0 += __shfl_xor_sync(0xffffffffu, s0, 1);
        s0 += __shfl_xor_sync(0xffffffffu, s0, 2);
        s1 += __shfl_xor_sync(0xffffffffu, s1, 1);
        s1 += __shfl_xor_sync(0xffffffffu, s1, 2);
        rl0 = rl0 * a0 + s0;
        rl1 = rl1 * a1 + s1;
#pragma unroll
        for (int nt = 0; nt < 8; nt++) {
            o[nt][0] *= a0; o[nt][1] *= a0; o[nt][2] *= a1; o[nt][3] *= a1;
        }

        // ---- O += P V (3-MMA split; P frags built in registers) ----
        uint32_t vb = kb + 16384;
#pragma unroll
        for (int ks = 0; ks < 4; ks++) {
            uint32_t ah[4], al[4];
            split2(sc[2 * ks][0],     sc[2 * ks][1],     ah[0], al[0]);
            split2(sc[2 * ks][2],     sc[2 * ks][3],     ah[1], al[1]);
            split2(sc[2 * ks + 1][0], sc[2 * ks + 1][1], ah[2], al[2]);
            split2(sc[2 * ks + 1][2], sc[2 * ks + 1][3], ah[3], al[3]);

            uint32_t bf[8][2];
#pragma unroll
            for (int dp = 0; dp < 4; dp++) {
                int row = ks * 16 + (qq & 1) * 8 + r;
                int cc = dp * 2 + (qq >> 1);
                uint32_t tt[4];
                ldsm4t(tt, vb + row * 128 + ((cc ^ (row & 7)) << 4));
                bf[2 * dp][0] = tt[0]; bf[2 * dp][1] = tt[1];
                bf[2 * dp + 1][0] = tt[2]; bf[2 * dp + 1][1] = tt[3];
            }
#pragma unroll
            for (int nt = 0; nt < 8; nt++) {
                mma16816(o[nt], ah, bf[nt]);
                mma16816(o[nt], al, bf[nt]);
            }
#pragma unroll
            for (int dp = 0; dp < 4; dp++) {
                int row = ks * 16 + (qq & 1) * 8 + r;
                int cc = dp * 2 + (qq >> 1);
                uint32_t tt[4];
                ldsm4t(tt, vb + 8192 + row * 128 + ((cc ^ (row & 7)) << 4));
                bf[2 * dp][0] = tt[0]; bf[2 * dp][1] = tt[1];
                bf[2 * dp + 1][0] = tt[2]; bf[2 * dp + 1][1] = tt[3];
            }
#pragma unroll
            for (int nt = 0; nt < 8; nt++)
                mma16816(o[nt], ah, bf[nt]);
        }
    }

    // ---- finalize + store ----
    float i0 = 1.f / rl0, i1 = 1.f / rl1;
#pragma unroll
    for (int nt = 0; nt < 8; nt++) {
        int dc = h * HD_ + nt * 8 + 2 * t;
        if (rq0 < S_)
            *(float2*)&out[((size_t)b * S_ + rq0) * D_ + dc] =
                make_float2(o[nt][0] * i0, o[nt][1] * i0);
        if (rq1 < S_)
            *(float2*)&out[((size_t)b * S_ + rq1) * D_ + dc] =
                make_float2(o[nt][2] * i1, o[nt][3] * i1);
    }
}

// ---------------------------------------------------------------------------
extern "C" void kernel_launch(void* const* d_in, const int* in_sizes, int n_in,
                              void* d_out, int out_size)
{
    const float* hidden = (const float*)d_in[0];
    const float* bias   = (const float*)d_in[1];
    const float* Wq     = (const float*)d_in[2];
    const float* bq     = (const float*)d_in[3];
    const float* Wk     = (const float*)d_in[4];
    const float* bk     = (const float*)d_in[5];
    const float* Wv     = (const float*)d_in[6];
    const float* bv     = (const float*)d_in[7];
    float* out = (float*)d_out;

    cudaFuncSetAttribute(gemm_kernel,
                         cudaFuncAttributeMaxDynamicSharedMemorySize, GEMM_SMEM);
    cudaFuncSetAttribute(attn_kernel,
                         cudaFuncAttributeMaxDynamicSharedMemorySize, ATT_SMEM);

    convx_kernel<<<(M_PAD * D_ / 4 + 255) / 256, 256>>>(hidden);
    convw_kernel<<<dim3(24, 24, 3), 256>>>(Wq, Wk, Wv);
    {
        size_t tot = (size_t)H_ * S_ * S_;
        convb_kernel<<<(unsigned)((tot + 255) / 256), 256>>>(bias);
    }
    gemm_kernel<<<dim3(65, 6, 3), 256, GEMM_SMEM>>>(bq, bk, bv);

    dim3 g2((S_ + QT - 1) / QT, B_, H_);   // (17, 8, 12)
    attn_kernel<<<g2, 128, ATT_SMEM>>>(out);
}

// round 12
// speedup vs baseline: 3.4283x; 1.0455x over previous
#include <cuda_runtime.h>
#include <cuda_bf16.h>
#include <cstdint>

#define B_    8
#define S_    1025
#define D_    768
#define H_    12
#define HD_   64
#define M_TOT (B_ * S_)       // 8200
#define M_PAD 8320            // 65 * 128
#define SPAD  1028            // bias row pitch (floats), 16B-aligned

// ---------------------------------------------------------------------------
// Device scratch
// ---------------------------------------------------------------------------
__device__ __align__(128) __nv_bfloat16 g_qhi[(size_t)M_PAD * D_];
__device__ __align__(128) __nv_bfloat16 g_qlo[(size_t)M_PAD * D_];
__device__ __align__(128) __nv_bfloat16 g_khi[(size_t)M_PAD * D_];
__device__ __align__(128) __nv_bfloat16 g_klo[(size_t)M_PAD * D_];
__device__ __align__(128) __nv_bfloat16 g_vhi[(size_t)M_PAD * D_];
__device__ __align__(128) __nv_bfloat16 g_vlo[(size_t)M_PAD * D_];
__device__ __align__(128) __nv_bfloat16 g_xhi[(size_t)M_PAD * D_];
__device__ __align__(128) __nv_bfloat16 g_xlo[(size_t)M_PAD * D_];
__device__ __align__(128) __nv_bfloat16 g_wthi[(size_t)3 * D_ * D_];
__device__ __align__(128) __nv_bfloat16 g_wtlo[(size_t)3 * D_ * D_];
__device__ __align__(128) float g_biasp[(size_t)H_ * S_ * SPAD];   // padded rel_bias

// ---------------------------------------------------------------------------
// Base-ISA PTX helpers
// ---------------------------------------------------------------------------
__device__ __forceinline__ uint32_t smem_u32(const void* p) {
    uint32_t a;
    asm("{ .reg .u64 t; cvta.to.shared.u64 t, %1; cvt.u32.u64 %0, t; }"
        : "=r"(a) : "l"(p));
    return a;
}
__device__ __forceinline__ void cp_async16(uint32_t dst, const void* src) {
    asm volatile("cp.async.cg.shared.global [%0], [%1], 16;\n"
                 :: "r"(dst), "l"(src));
}
__device__ __forceinline__ void ldsm4(uint32_t* r, uint32_t addr) {
    asm volatile("ldmatrix.sync.aligned.m8n8.x4.shared.b16 {%0,%1,%2,%3}, [%4];\n"
                 : "=r"(r[0]), "=r"(r[1]), "=r"(r[2]), "=r"(r[3]) : "r"(addr));
}
__device__ __forceinline__ void ldsm4t(uint32_t* r, uint32_t addr) {
    asm volatile("ldmatrix.sync.aligned.m8n8.x4.trans.shared.b16 {%0,%1,%2,%3}, [%4];\n"
                 : "=r"(r[0]), "=r"(r[1]), "=r"(r[2]), "=r"(r[3]) : "r"(addr));
}
__device__ __forceinline__ void mma16816(float* d, const uint32_t* a,
                                         const uint32_t* b) {
    asm volatile(
        "mma.sync.aligned.m16n8k16.row.col.f32.bf16.bf16.f32 "
        "{%0,%1,%2,%3}, {%4,%5,%6,%7}, {%8,%9}, {%0,%1,%2,%3};\n"
        : "+f"(d[0]), "+f"(d[1]), "+f"(d[2]), "+f"(d[3])
        : "r"(a[0]), "r"(a[1]), "r"(a[2]), "r"(a[3]), "r"(b[0]), "r"(b[1]));
}
__device__ __forceinline__ void split2(float x, float y, uint32_t& hi, uint32_t& lo) {
    __nv_bfloat162 h = __floats2bfloat162_rn(x, y);
    float2 f = __bfloat1622float2(h);
    __nv_bfloat162 l = __floats2bfloat162_rn(x - f.x, y - f.y);
    hi = *(uint32_t*)&h;
    lo = *(uint32_t*)&l;
}

// ---------------------------------------------------------------------------
// Conversion: X -> (hi, lo) bf16, rows >= 8200 zeroed (pad to 8320)
// ---------------------------------------------------------------------------
__global__ __launch_bounds__(256) void convx_kernel(const float* __restrict__ X)
{
    size_t i = ((size_t)blockIdx.x * 256 + threadIdx.x) * 4;
    if (i >= (size_t)M_PAD * D_) return;
    size_t m = i / D_;
    float4 x = (m < M_TOT) ? *(const float4*)&X[i] : make_float4(0.f, 0.f, 0.f, 0.f);
    uint2 uh, ul;
    split2(x.x, x.y, uh.x, ul.x);
    split2(x.z, x.w, uh.y, ul.y);
    *(uint2*)&g_xhi[i] = uh;
    *(uint2*)&g_xlo[i] = ul;
}

// ---------------------------------------------------------------------------
// Conversion: W^T -> (hi, lo) bf16, tiled transpose. Wt[n][k] = W[k][n].
// ---------------------------------------------------------------------------
__global__ __launch_bounds__(256) void convw_kernel(
    const float* __restrict__ Wq, const float* __restrict__ Wk,
    const float* __restrict__ Wv)
{
    __shared__ float t[32][33];
    const float* W = (blockIdx.z == 0) ? Wq : (blockIdx.z == 1) ? Wk : Wv;
    __nv_bfloat16* oh = g_wthi + (size_t)blockIdx.z * D_ * D_;
    __nv_bfloat16* ol = g_wtlo + (size_t)blockIdx.z * D_ * D_;
    int k0 = blockIdx.x * 32, n0 = blockIdx.y * 32;
    for (int i = threadIdx.x; i < 1024; i += 256) {
        int r = i >> 5, c = i & 31;
        t[r][c] = W[(size_t)(k0 + r) * D_ + n0 + c];
    }
    __syncthreads();
    for (int i = threadIdx.x; i < 1024; i += 256) {
        int r = i >> 5, c = i & 31;
        float x = t[c][r];
        __nv_bfloat16 h = __float2bfloat16(x);
        oh[(size_t)(n0 + r) * D_ + k0 + c] = h;
        ol[(size_t)(n0 + r) * D_ + k0 + c] =
            __float2bfloat16(x - __bfloat162float(h));
    }
}

// ---------------------------------------------------------------------------
// Repack rel_bias [H][S][S] -> g_biasp [H][S][SPAD] (rows 16B-aligned).
// ---------------------------------------------------------------------------
__global__ __launch_bounds__(256) void convb_kernel(const float* __restrict__ rb)
{
    size_t i = (size_t)blockIdx.x * 256 + threadIdx.x;
    const size_t tot = (size_t)H_ * S_ * S_;
    if (i >= tot) return;
    size_t row = i / S_;
    int col = (int)(i - row * S_);
    g_biasp[row * SPAD + col] = rb[i];
}

// ---------------------------------------------------------------------------
// mma.sync split-bf16 GEMM. R12: 128-thread CTAs (4 warps, tile 128x64,
// warp tile 32x64 unchanged), 2 CTAs/SM so load/sync phases of one CTA
// overlap MMA phases of the other. grid = (65, 12, 3).
// Stage (48KB): Ahi 16K | Alo 16K | Bhi 8K | Blo 8K. 2 stages = 96KB.
// ---------------------------------------------------------------------------
#define STAGE_BYTES 49152
#define A_LO    16384
#define B_OFF   32768
#define B_LO    8192
#define GEMM_SMEM   (2 * STAGE_BYTES)

__global__ __launch_bounds__(128, 2) void gemm_kernel(
    const float* __restrict__ bq, const float* __restrict__ bk,
    const float* __restrict__ bv)
{
    extern __shared__ __align__(1024) unsigned char smg[];
    uint32_t sb = smem_u32(smg);
    int tid = threadIdx.x, wid = tid >> 5, lid = tid & 31;
    int m0 = blockIdx.x * 128;
    int n0 = blockIdx.y * 64;
    int mat = blockIdx.z;

    const __nv_bfloat16* Bhi = g_wthi + (size_t)mat * D_ * D_;
    const __nv_bfloat16* Blo = g_wtlo + (size_t)mat * D_ * D_;
    __nv_bfloat16* ohi = (mat == 0) ? g_qhi : (mat == 1) ? g_khi : g_vhi;
    __nv_bfloat16* olo = (mat == 0) ? g_qlo : (mat == 1) ? g_klo : g_vlo;
    const float* bias = (mat == 0) ? bq : (mat == 1) ? bk : bv;
    const float osc = (mat == 0) ? 0.125f : 1.0f;

    float acc[2][8][4];
#pragma unroll
    for (int f = 0; f < 2; f++)
#pragma unroll
        for (int nf = 0; nf < 8; nf++)
#pragma unroll
            for (int j = 0; j < 4; j++) acc[f][nf][j] = 0.f;

    auto load_stage = [&](int c, int s) {
        int k0 = c * 64;
        uint32_t st = sb + s * STAGE_BYTES;
        // A: 2 splits x 128 rows x 8 chunks = 2048 chunks
#pragma unroll
        for (int pass = 0; pass < 16; pass++) {
            int idx = pass * 128 + tid;
            int sp = idx >> 10, rem = idx & 1023;
            int row = rem >> 3, cc = rem & 7;
            const __nv_bfloat16* src =
                (sp ? g_xlo : g_xhi) + (size_t)(m0 + row) * D_ + k0 + cc * 8;
            cp_async16(st + sp * A_LO + row * 128 + ((cc ^ (row & 7)) << 4), src);
        }
        // B: 2 splits x 64 rows x 8 chunks = 1024 chunks
#pragma unroll
        for (int pass = 0; pass < 8; pass++) {
            int idx = pass * 128 + tid;
            int sp = idx >> 9, rem = idx & 511;
            int row = rem >> 3, cc = rem & 7;
            const __nv_bfloat16* src =
                (sp ? Blo : Bhi) + (size_t)(n0 + row) * D_ + k0 + cc * 8;
            cp_async16(st + B_OFF + sp * B_LO + row * 128 + ((cc ^ (row & 7)) << 4), src);
        }
        asm volatile("cp.async.commit_group;\n" ::: "memory");
    };

    load_stage(0, 0);

    for (int c = 0; c < 12; c++) {
        int s = c & 1;
        if (c + 1 < 12) {
            load_stage(c + 1, s ^ 1);
            asm volatile("cp.async.wait_group 1;\n" ::: "memory");
        } else {
            asm volatile("cp.async.wait_group 0;\n" ::: "memory");
        }
        __syncthreads();

        uint32_t st  = sb + s * STAGE_BYTES;
        uint32_t bB  = st + B_OFF;
        int q = lid >> 3, r = lid & 7;

#pragma unroll
        for (int ks = 0; ks < 4; ks++) {
            uint32_t ah[2][4], alr[2][4];
#pragma unroll
            for (int f = 0; f < 2; f++) {
                int mrow = wid * 32 + f * 16 + (q & 1) * 8 + r;
                int cc   = ks * 2 + (q >> 1);
                uint32_t addr = st + mrow * 128 + ((cc ^ (mrow & 7)) << 4);
                ldsm4(ah[f], addr);
                ldsm4(alr[f], addr + A_LO);
            }
            uint32_t bb[8][2];
#pragma unroll
            for (int g = 0; g < 4; g++) {
                int nrow = g * 16 + (q >> 1) * 8 + r;
                int cc   = ks * 2 + (q & 1);
                uint32_t t[4];
                ldsm4(t, bB + nrow * 128 + ((cc ^ (nrow & 7)) << 4));
                bb[2 * g][0] = t[0]; bb[2 * g][1] = t[1];
                bb[2 * g + 1][0] = t[2]; bb[2 * g + 1][1] = t[3];
            }
#pragma unroll
            for (int f = 0; f < 2; f++)
#pragma unroll
                for (int nf = 0; nf < 8; nf++) {
                    mma16816(acc[f][nf], ah[f], bb[nf]);
                    mma16816(acc[f][nf], alr[f], bb[nf]);
                }
#pragma unroll
            for (int g = 0; g < 4; g++) {
                int nrow = g * 16 + (q >> 1) * 8 + r;
                int cc   = ks * 2 + (q & 1);
                uint32_t t[4];
                ldsm4(t, bB + B_LO + nrow * 128 + ((cc ^ (nrow & 7)) << 4));
                bb[2 * g][0] = t[0]; bb[2 * g][1] = t[1];
                bb[2 * g + 1][0] = t[2]; bb[2 * g + 1][1] = t[3];
            }
#pragma unroll
            for (int f = 0; f < 2; f++)
#pragma unroll
                for (int nf = 0; nf < 8; nf++)
                    mma16816(acc[f][nf], ah[f], bb[nf]);
        }
        __syncthreads();
    }

    // ---- epilogue: split-bf16 hi/lo + bias (+0.125 scale for Q) ----
    int g2 = lid >> 2, tg = lid & 3;
    int mbase = m0 + wid * 32;
#pragma unroll
    for (int f = 0; f < 2; f++) {
#pragma unroll
        for (int nf = 0; nf < 8; nf++) {
            int n = n0 + nf * 8 + tg * 2;
            float b0 = bias[n], b1 = bias[n + 1];
            int m = mbase + f * 16 + g2;
            if (m < M_TOT) {
                uint32_t h, l;
                split2((acc[f][nf][0] + b0) * osc, (acc[f][nf][1] + b1) * osc, h, l);
                *(uint32_t*)&ohi[(size_t)m * D_ + n] = h;
                *(uint32_t*)&olo[(size_t)m * D_ + n] = l;
            }
            if (m + 8 < M_TOT) {
                uint32_t h, l;
                split2((acc[f][nf][2] + b0) * osc, (acc[f][nf][3] + b1) * osc, h, l);
                *(uint32_t*)&ohi[(size_t)(m + 8) * D_ + n] = h;
                *(uint32_t*)&olo[(size_t)(m + 8) * D_ + n] = l;
            }
        }
    }
}

// ---------------------------------------------------------------------------
// Tensor-core flash attention (unchanged from R11 — validated at ~250us).
// ---------------------------------------------------------------------------
#define QT   64
#define NKT  17
#define BIAS_OFF 32768
#define KVST (32768 + 64 * 272)          // 50176 per stage
#define ATT_SMEM (2 * KVST)              // 100352

__global__ __launch_bounds__(128, 2) void attn_kernel(float* __restrict__ out)
{
    extern __shared__ __align__(1024) unsigned char sma[];
    uint32_t sb = smem_u32(sma);
    int tid = threadIdx.x, wid = tid >> 5, lid = tid & 31;
    int qq = lid >> 3, r = lid & 7;       // ldmatrix lane decomposition
    int g  = lid >> 2, t = lid & 3;       // mma accum lane decomposition
    int q0 = blockIdx.x * QT;
    int b  = blockIdx.y;
    int h  = blockIdx.z;

    const __nv_bfloat16* arrp[4] = {g_khi, g_klo, g_vhi, g_vlo};

    auto load_q = [&]() {
#pragma unroll
        for (int p = 0; p < 8; p++) {
            int idx = p * 128 + tid;                 // 1024 chunks
            int sp = idx >> 9, rem = idx & 511;
            int row = rem >> 3, cc = rem & 7;
            int gq = q0 + row; if (gq > S_ - 1) gq = S_ - 1;
            const __nv_bfloat16* src = (sp ? g_qlo : g_qhi)
                + (size_t)(b * S_ + gq) * D_ + h * HD_ + cc * 8;
            cp_async16(sb + sp * 8192 + row * 128 + ((cc ^ (row & 7)) << 4), src);
        }
        asm volatile("cp.async.commit_group;\n" ::: "memory");
    };
    auto load_kv = [&](int kt, int s) {
#pragma unroll
        for (int p = 0; p < 16; p++) {
            int idx = p * 128 + tid;                 // 2048 chunks
            int a = idx >> 9, rem = idx & 511;
            int row = rem >> 3, cc = rem & 7;
            int gk = kt * 64 + row; if (gk > S_ - 1) gk = S_ - 1;
            const __nv_bfloat16* src = arrp[a]
                + (size_t)(b * S_ + gk) * D_ + h * HD_ + cc * 8;
            cp_async16(sb + s * KVST + a * 8192 + row * 128 + ((cc ^ (row & 7)) << 4), src);
        }
        // bias tile: 64 q-rows x 64 keys fp32 from padded buffer (16B rows)
#pragma unroll
        for (int p = 0; p < 8; p++) {
            int idx = p * 128 + tid;                 // 1024 chunks
            int row = idx >> 4, cc = idx & 15;
            int gq = q0 + row; if (gq > S_ - 1) gq = S_ - 1;
            int kc = kt * 64 + cc * 4;
            const float* src = g_biasp + ((size_t)h * S_ + gq) * SPAD + kc;
            cp_async16(sb + s * KVST + BIAS_OFF + row * 272 + cc * 16, src);
        }
        asm volatile("cp.async.commit_group;\n" ::: "memory");
    };

    load_q();
    load_kv(0, 1);
    asm volatile("cp.async.wait_group 1;\n" ::: "memory");
    __syncthreads();

    // Extract Q A-fragments (hi+lo) to registers.
    uint32_t qh[4][4], qlr[4][4];
#pragma unroll
    for (int ks = 0; ks < 4; ks++) {
        int mrow = wid * 16 + (qq & 1) * 8 + r;
        int cc = ks * 2 + (qq >> 1);
        uint32_t addr = sb + mrow * 128 + ((cc ^ (mrow & 7)) << 4);
        ldsm4(qh[ks], addr);
        ldsm4(qlr[ks], addr + 8192);
    }
    __syncthreads();    // stage-0 region now reusable for KV

    float o[8][4];
#pragma unroll
    for (int nt = 0; nt < 8; nt++)
#pragma unroll
        for (int j = 0; j < 4; j++) o[nt][j] = 0.f;
    float rm0 = -1e30f, rm1 = -1e30f, rl0 = 0.f, rl1 = 0.f;

    int rq0 = q0 + wid * 16 + g;
    int rq1 = rq0 + 8;

    for (int it = 0; it < NKT; it++) {
        int s = (it + 1) & 1;
        __syncthreads();                       // prior compute done -> s^1 reusable
        if (it + 1 < NKT) {
            load_kv(it + 1, s ^ 1);
            asm volatile("cp.async.wait_group 1;\n" ::: "memory");
        } else {
            asm volatile("cp.async.wait_group 0;\n" ::: "memory");
        }
        __syncthreads();                       // stage s visible to all

        uint32_t kb = sb + s * KVST;
        float sc[8][4];
#pragma unroll
        for (int nt = 0; nt < 8; nt++)
#pragma unroll
            for (int j = 0; j < 4; j++) sc[nt][j] = 0.f;

        // ---- S = Q' K^T (3-MMA split) ----
#pragma unroll
        for (int ks = 0; ks < 4; ks++) {
            uint32_t bf[8][2];
#pragma unroll
            for (int gg = 0; gg < 4; gg++) {
                int nrow = gg * 16 + (qq >> 1) * 8 + r;
                int cc = ks * 2 + (qq & 1);
                uint32_t tt[4];
                ldsm4(tt, kb + nrow * 128 + ((cc ^ (nrow & 7)) << 4));
                bf[2 * gg][0] = tt[0]; bf[2 * gg][1] = tt[1];
                bf[2 * gg + 1][0] = tt[2]; bf[2 * gg + 1][1] = tt[3];
            }
#pragma unroll
            for (int nt = 0; nt < 8; nt++) {
                mma16816(sc[nt], qh[ks], bf[nt]);
                mma16816(sc[nt], qlr[ks], bf[nt]);
            }
#pragma unroll
            for (int gg = 0; gg < 4; gg++) {
                int nrow = gg * 16 + (qq >> 1) * 8 + r;
                int cc = ks * 2 + (qq & 1);
                uint32_t tt[4];
                ldsm4(tt, kb + 8192 + nrow * 128 + ((cc ^ (nrow & 7)) << 4));
                bf[2 * gg][0] = tt[0]; bf[2 * gg][1] = tt[1];
                bf[2 * gg + 1][0] = tt[2]; bf[2 * gg + 1][1] = tt[3];
            }
#pragma unroll
            for (int nt = 0; nt < 8; nt++)
                mma16816(sc[nt], qh[ks], bf[nt]);
        }

        // ---- bias (from smem) + mask + online softmax ----
        const float* bsm = (const float*)(sma + s * KVST + BIAS_OFF);
        const float* br0 = bsm + (wid * 16 + g) * 68 + 2 * t;
        const float* br1 = br0 + 8 * 68;
        int kbase = it * 64;
        float nx0 = rm0, nx1 = rm1;
#pragma unroll
        for (int nt = 0; nt < 8; nt++) {
            int kc = kbase + nt * 8 + 2 * t;
            bool v0 = kc < S_, v1 = (kc + 1) < S_;
            float2 b0 = *(const float2*)(br0 + nt * 8);
            float2 b1 = *(const float2*)(br1 + nt * 8);
            sc[nt][0] = v0 ? sc[nt][0] + b0.x : -1e30f;
            sc[nt][1] = v1 ? sc[nt][1] + b0.y : -1e30f;
            sc[nt][2] = v0 ? sc[nt][2] + b1.x : -1e30f;
            sc[nt][3] = v1 ? sc[nt][3] + b1.y : -1e30f;
            nx0 = fmaxf(nx0, fmaxf(sc[nt][0], sc[nt][1]));
            nx1 = fmaxf(nx1, fmaxf(sc[nt][2], sc[nt][3]));
        }
        nx0 = fmaxf(nx0, __shfl_xor_sync(0xffffffffu, nx0, 1));
        nx0 = fmaxf(nx0, __shfl_xor_sync(0xffffffffu, nx0, 2));
        nx1 = fmaxf(nx1, __shfl_xor_sync(0xffffffffu, nx1, 1));
        nx1 = fmaxf(nx1, __shfl_xor_sync(0xffffffffu, nx1, 2));
        float a0 = __expf(rm0 - nx0), a1 = __expf(rm1 - nx1);
        rm0 = nx0; rm1 = nx1;
        float s0 = 0.f, s1 = 0.f;
#pragma unroll
        for (int nt = 0; nt < 8; nt++) {
            sc[nt][0] = __expf(sc[nt][0] - nx0);
            sc[nt][1] = __expf(sc[nt][1] - nx0);
            sc[nt][2] = __expf(sc[nt][2] - nx1);
            sc[nt][3] = __expf(sc[nt][3] - nx1);
            s0 += sc[nt][0] + sc[nt][1];
            s1 += sc[nt][2] + sc[nt][3];
        }
        s0 += __shfl_xor_sync(0xffffffffu, s0, 1);
        s0 += __shfl_xor_sync(0xffffffffu, s0, 2);
        s1 += __shfl_xor_sync(0xffffffffu, s1, 1);
        s1 += __shfl_xor_sync(0xffffffffu, s1, 2);
        rl0 = rl0 * a0 + s0;
        rl1 = rl1 * a1 + s1;
#pragma unroll
        for (int nt = 0; nt < 8; nt++) {
            o[nt][0] *= a0; o[nt][1] *= a0; o[nt][2] *= a1; o[nt][3] *= a1;
        }

        // ---- O += P V (3-MMA split; P frags built in registers) ----
        uint32_t vb = kb + 16384;
#pragma unroll
        for (int ks = 0; ks < 4; ks++) {
            uint32_t ah[4], al[4];
            split2(sc[2 * ks][0],     sc[2 * ks][1],     ah[0], al[0]);
            split2(sc[2 * ks][2],     sc[2 * ks][3],     ah[1], al[1]);
            split2(sc[2 * ks + 1][0], sc[2 * ks + 1][1], ah[2], al[2]);
            split2(sc[2 * ks + 1][2], sc[2 * ks + 1][3], ah[3], al[3]);

            uint32_t bf[8][2];
#pragma unroll
            for (int dp = 0; dp < 4; dp++) {
                int row = ks * 16 + (qq & 1) * 8 + r;
                int cc = dp * 2 + (qq >> 1);
                uint32_t tt[4];
                ldsm4t(tt, vb + row * 128 + ((cc ^ (row & 7)) << 4));
                bf[2 * dp][0] = tt[0]; bf[2 * dp][1] = tt[1];
                bf[2 * dp + 1][0] = tt[2]; bf[2 * dp + 1][1] = tt[3];
            }
#pragma unroll
            for (int nt = 0; nt < 8; nt++) {
                mma16816(o[nt], ah, bf[nt]);
                mma16816(o[nt], al, bf[nt]);
            }
#pragma unroll
            for (int dp = 0; dp < 4; dp++) {
                int row = ks * 16 + (qq & 1) * 8 + r;
                int cc = dp * 2 + (qq >> 1);
                uint32_t tt[4];
                ldsm4t(tt, vb + 8192 + row * 128 + ((cc ^ (row & 7)) << 4));
                bf[2 * dp][0] = tt[0]; bf[2 * dp][1] = tt[1];
                bf[2 * dp + 1][0] = tt[2]; bf[2 * dp + 1][1] = tt[3];
            }
#pragma unroll
            for (int nt = 0; nt < 8; nt++)
                mma16816(o[nt], ah, bf[nt]);
        }
    }

    // ---- finalize + store ----
    float i0 = 1.f / rl0, i1 = 1.f / rl1;
#pragma unroll
    for (int nt = 0; nt < 8; nt++) {
        int dc = h * HD_ + nt * 8 + 2 * t;
        if (rq0 < S_)
            *(float2*)&out[((size_t)b * S_ + rq0) * D_ + dc] =
                make_float2(o[nt][0] * i0, o[nt][1] * i0);
        if (rq1 < S_)
            *(float2*)&out[((size_t)b * S_ + rq1) * D_ + dc] =
                make_float2(o[nt][2] * i1, o[nt][3] * i1);
    }
}

// ---------------------------------------------------------------------------
extern "C" void kernel_launch(void* const* d_in, const int* in_sizes, int n_in,
                              void* d_out, int out_size)
{
    const float* hidden = (const float*)d_in[0];
    const float* bias   = (const float*)d_in[1];
    const float* Wq     = (const float*)d_in[2];
    const float* bq     = (const float*)d_in[3];
    const float* Wk     = (const float*)d_in[4];
    const float* bk     = (const float*)d_in[5];
    const float* Wv     = (const float*)d_in[6];
    const float* bv     = (const float*)d_in[7];
    float* out = (float*)d_out;

    cudaFuncSetAttribute(gemm_kernel,
                         cudaFuncAttributeMaxDynamicSharedMemorySize, GEMM_SMEM);
    cudaFuncSetAttribute(attn_kernel,
                         cudaFuncAttributeMaxDynamicSharedMemorySize, ATT_SMEM);

    convx_kernel<<<(M_PAD * D_ / 4 + 255) / 256, 256>>>(hidden);
    convw_kernel<<<dim3(24, 24, 3), 256>>>(Wq, Wk, Wv);
    {
        size_t tot = (size_t)H_ * S_ * S_;
        convb_kernel<<<(unsigned)((tot + 255) / 256), 256>>>(bias);
    }
    gemm_kernel<<<dim3(65, 12, 3), 128, GEMM_SMEM>>>(bq, bk, bv);

    dim3 g2((S_ + QT - 1) / QT, B_, H_);   // (17, 8, 12)
    attn_kernel<<<g2, 128, ATT_SMEM>>>(out);
}